// round 2
// baseline (speedup 1.0000x reference)
#include <cuda_runtime.h>
#include <math.h>

#define BB 2
#define TT 2048
#define CC 1024
#define HH 16
#define DD 64
#define MM (BB*TT)   // 4096 rows

// Scratch (allocation-free: __device__ globals)
__device__ float g_qkv[(size_t)BB*TT*3*CC];  // [B,T,3C]
__device__ float g_ao [(size_t)BB*TT*CC];    // [B,T,C]

// ---------------------------------------------------------------------------
// Tiled fp32 GEMM with bias: out[M,N] = A[M,K] @ W[K,N] + bias[N]
// 64x64 block tile, BK=16, 256 threads, 4x4 micro-tile per thread.
// ---------------------------------------------------------------------------
__global__ void gemm_bias_kernel(const float* __restrict__ A,
                                 const float* __restrict__ W,
                                 const float* __restrict__ bias,
                                 float* __restrict__ out,
                                 int M, int N, int K)
{
    __shared__ float As[16][68];   // As[kk][m], stride 68*4=272B (16B aligned)
    __shared__ float Bs[16][68];   // Bs[kk][n]

    const int tid = threadIdx.x;
    const int tx  = tid & 15;      // N direction
    const int ty  = tid >> 4;      // M direction
    const int bm  = blockIdx.y * 64;
    const int bn  = blockIdx.x * 64;

    float acc[4][4];
    #pragma unroll
    for (int i = 0; i < 4; i++)
        #pragma unroll
        for (int j = 0; j < 4; j++) acc[i][j] = 0.f;

    for (int k0 = 0; k0 < K; k0 += 16) {
        #pragma unroll
        for (int l = 0; l < 4; l++) {
            int idx = tid + l*256;            // 0..1023
            int m = idx >> 4, kk = idx & 15;  // 64 x 16
            As[kk][m] = A[(size_t)(bm + m)*K + k0 + kk];
        }
        #pragma unroll
        for (int l = 0; l < 4; l++) {
            int idx = tid + l*256;
            int kk = idx >> 6, n = idx & 63;  // 16 x 64
            Bs[kk][n] = W[(size_t)(k0 + kk)*N + bn + n];
        }
        __syncthreads();

        #pragma unroll
        for (int kk = 0; kk < 16; kk++) {
            float4 a4 = *(const float4*)&As[kk][ty*4];
            float4 b4 = *(const float4*)&Bs[kk][tx*4];
            float a[4] = {a4.x, a4.y, a4.z, a4.w};
            float b[4] = {b4.x, b4.y, b4.z, b4.w};
            #pragma unroll
            for (int i = 0; i < 4; i++)
                #pragma unroll
                for (int j = 0; j < 4; j++)
                    acc[i][j] += a[i]*b[j];
        }
        __syncthreads();
    }

    #pragma unroll
    for (int i = 0; i < 4; i++) {
        int m = bm + ty*4 + i;
        #pragma unroll
        for (int j = 0; j < 4; j++) {
            int n = bn + tx*4 + j;
            out[(size_t)m*N + n] = acc[i][j] + bias[n];
        }
    }
}

// ---------------------------------------------------------------------------
// Causal flash attention, fp32.
// grid = (T/64, H, B), block = 128 threads.
// 2 threads per q-row; each owns 32 of the 64 head dims.
// Online softmax over 8-key chunks. Tiles strictly above the diagonal skipped.
// ---------------------------------------------------------------------------
__global__ void attn_kernel(const float* __restrict__ qkv, float* __restrict__ ao)
{
    const int qt  = blockIdx.x;
    const int h   = blockIdx.y;
    const int b   = blockIdx.z;
    const int tid = threadIdx.x;
    const int row  = tid >> 1;      // 0..63
    const int half = tid & 1;       // which 32-dim half
    const int qg   = qt*64 + row;   // global q position

    __shared__ float ks[64][68];
    __shared__ float vs[64][68];

    const float scale = 0.125f;     // 1/sqrt(64)

    // Load q row (pre-scaled) into registers
    float q[32];
    {
        const float* qp = qkv + (size_t)(b*TT + qg)*3*CC + h*DD + half*32;
        #pragma unroll
        for (int i = 0; i < 8; i++) {
            float4 f = *(const float4*)(qp + i*4);
            q[i*4+0] = f.x*scale; q[i*4+1] = f.y*scale;
            q[i*4+2] = f.z*scale; q[i*4+3] = f.w*scale;
        }
    }

    float acc[32];
    #pragma unroll
    for (int i = 0; i < 32; i++) acc[i] = 0.f;
    float mrun = -1e30f, lrun = 0.f;

    for (int kt = 0; kt <= qt; kt++) {
        // Load K/V tiles [64,64] into shared (float4, coalesced per row chunk)
        const float* kb = qkv + (size_t)(b*TT + kt*64)*3*CC + CC + h*DD;
        const float* vb = kb + CC;
        #pragma unroll
        for (int l = 0; l < 8; l++) {
            int idx = tid + l*128;           // 0..1023 float4 slots
            int r = idx >> 4, c4 = idx & 15; // 64 rows x 16 float4
            *(float4*)&ks[r][c4*4] = *(const float4*)(kb + (size_t)r*3*CC + c4*4);
            *(float4*)&vs[r][c4*4] = *(const float4*)(vb + (size_t)r*3*CC + c4*4);
        }
        __syncthreads();

        const bool diag = (kt == qt);

        #pragma unroll 2
        for (int kc = 0; kc < 64; kc += 8) {
            float s[8];
            #pragma unroll
            for (int j = 0; j < 8; j++) {
                const float4* kr = (const float4*)&ks[kc+j][half*32];
                float sum = 0.f;
                #pragma unroll
                for (int d4 = 0; d4 < 8; d4++) {
                    float4 k4 = kr[d4];
                    sum += q[d4*4+0]*k4.x + q[d4*4+1]*k4.y
                         + q[d4*4+2]*k4.z + q[d4*4+3]*k4.w;
                }
                sum += __shfl_xor_sync(0xffffffffu, sum, 1);  // combine halves
                if (diag && (kt*64 + kc + j) > qg) sum = -1e30f;
                s[j] = sum;
            }

            float mnew = mrun;
            #pragma unroll
            for (int j = 0; j < 8; j++) mnew = fmaxf(mnew, s[j]);
            float alpha = __expf(mrun - mnew);
            mrun = mnew;
            lrun *= alpha;
            #pragma unroll
            for (int d = 0; d < 32; d++) acc[d] *= alpha;

            #pragma unroll
            for (int j = 0; j < 8; j++) {
                float p = __expf(s[j] - mnew);
                lrun += p;
                const float4* vr = (const float4*)&vs[kc+j][half*32];
                #pragma unroll
                for (int d4 = 0; d4 < 8; d4++) {
                    float4 v4 = vr[d4];
                    acc[d4*4+0] += p*v4.x; acc[d4*4+1] += p*v4.y;
                    acc[d4*4+2] += p*v4.z; acc[d4*4+3] += p*v4.w;
                }
            }
        }
        __syncthreads();
    }

    const float inv = 1.f / lrun;
    float* op = ao + (size_t)(b*TT + qg)*CC + h*DD + half*32;
    #pragma unroll
    for (int i = 0; i < 8; i++) {
        float4 o;
        o.x = acc[i*4+0]*inv; o.y = acc[i*4+1]*inv;
        o.z = acc[i*4+2]*inv; o.w = acc[i*4+3]*inv;
        *(float4*)(op + i*4) = o;
    }
}

// ---------------------------------------------------------------------------
extern "C" void kernel_launch(void* const* d_in, const int* in_sizes, int n_in,
                              void* d_out, int out_size)
{
    const float* x     = (const float*)d_in[0];
    const float* Wqkv  = (const float*)d_in[1];
    const float* bqkv  = (const float*)d_in[2];
    const float* Wproj = (const float*)d_in[3];
    const float* bproj = (const float*)d_in[4];
    float* out = (float*)d_out;

    float *qkv = nullptr, *ao = nullptr;
    cudaGetSymbolAddress((void**)&qkv, g_qkv);
    cudaGetSymbolAddress((void**)&ao,  g_ao);

    // 1) QKV projection: [4096,1024] @ [1024,3072] + bias
    gemm_bias_kernel<<<dim3(3*CC/64, MM/64), 256>>>(x, Wqkv, bqkv, qkv, MM, 3*CC, CC);

    // 2) Causal attention -> [B,T,C]
    attn_kernel<<<dim3(TT/64, HH, BB), 128>>>(qkv, ao);

    // 3) Output projection: [4096,1024] @ [1024,1024] + bias
    gemm_bias_kernel<<<dim3(CC/64, MM/64), 256>>>(ao, Wproj, bproj, out, MM, CC, CC);
}

// round 5
// speedup vs baseline: 1.6778x; 1.6778x over previous
#include <cuda_runtime.h>
#include <math.h>
#include <cstdint>

#define BB 2
#define TT 2048
#define CC 1024
#define HH 16
#define DD 64
#define MM (BB*TT)   // 4096 rows

// Scratch (allocation-free: __device__ globals)
__device__ float g_qkv[(size_t)BB*TT*3*CC];  // [B,T,3C]
__device__ float g_ao [(size_t)BB*TT*CC];    // [B,T,C]
__device__ float g_wt [(size_t)3*CC*CC];     // W_qkv^T  [3C, C]
__device__ float g_wt2[(size_t)CC*CC];       // W_proj^T [C, C]

// ===========================================================================
// helpers (sm_80-era only: cp.async + mma.sync; no 'a'-gated instructions)
// ===========================================================================
__device__ __forceinline__ uint32_t smem_u32(const void* p) {
    uint32_t a;
    asm("{ .reg .u64 t; cvta.to.shared.u64 t, %1; cvt.u32.u64 %0, t; }"
        : "=r"(a) : "l"(p));
    return a;
}
__device__ __forceinline__ void cp_async16(uint32_t dst, const void* src) {
    asm volatile("cp.async.cg.shared.global [%0], [%1], 16;\n"
                 :: "r"(dst), "l"(src));
}
__device__ __forceinline__ void cp_commit() {
    asm volatile("cp.async.commit_group;\n" ::: "memory");
}
template<int N> __device__ __forceinline__ void cp_wait() {
    asm volatile("cp.async.wait_group %0;\n" :: "n"(N) : "memory");
}
__device__ __forceinline__ uint32_t f2tf32(float f) {
    uint32_t r;
    asm("cvt.rna.tf32.f32 %0, %1;" : "=r"(r) : "f"(f));
    return r;
}
__device__ __forceinline__ void mma_tf32(float c[4],
                                         const uint32_t a[4],
                                         const uint32_t b[2]) {
    asm volatile(
        "mma.sync.aligned.m16n8k8.row.col.f32.tf32.tf32.f32 "
        "{%0,%1,%2,%3}, {%4,%5,%6,%7}, {%8,%9}, {%0,%1,%2,%3};"
        : "+f"(c[0]), "+f"(c[1]), "+f"(c[2]), "+f"(c[3])
        : "r"(a[0]), "r"(a[1]), "r"(a[2]), "r"(a[3]),
          "r"(b[0]), "r"(b[1]));
}

// ===========================================================================
// Weight transpose: out[C,R] = in[R,C]^T
// ===========================================================================
__global__ void transpose_kernel(const float* __restrict__ in,
                                 float* __restrict__ out, int R, int C)
{
    __shared__ float t[32][33];
    int bx = blockIdx.x * 32, by = blockIdx.y * 32;
    #pragma unroll
    for (int i = 0; i < 32; i += 8)
        t[threadIdx.y + i][threadIdx.x] =
            in[(size_t)(by + threadIdx.y + i) * C + bx + threadIdx.x];
    __syncthreads();
    #pragma unroll
    for (int i = 0; i < 32; i += 8)
        out[(size_t)(bx + threadIdx.y + i) * R + by + threadIdx.x] =
            t[threadIdx.x][threadIdx.y + i];
}

// ===========================================================================
// tf32 mma.sync GEMM with bias: out[M,N] = A[M,K] @ Bt[N,K]^T + bias[N]
// CTA 128x128 tile, 256 threads (8 warps, 4x2), K chunk 32, 2-stage cp.async.
// Both operands K-major rows in smem, padded to 36 floats (conflict-free:
// bank = (4*grp + qd) % 32 covers all 32 banks).
// ===========================================================================
#define KCH 32
#define PAD 36
#define OPER_W (128*PAD)                       // floats per operand per stage
#define SMEM_GEMM (4*OPER_W*4)                 // 2 stages * 2 operands * 4B

__global__ void __launch_bounds__(256) gemm_mma(const float* __restrict__ A,
                                                const float* __restrict__ Bt,
                                                const float* __restrict__ bias,
                                                float* __restrict__ out,
                                                int M, int N, int K)
{
    extern __shared__ float sm[];
    float* As = sm;                 // [2][128][PAD]
    float* Bs = sm + 2*OPER_W;      // [2][128][PAD]
    const uint32_t As_u = smem_u32(As);
    const uint32_t Bs_u = smem_u32(Bs);

    const int tid  = threadIdx.x;
    const int wid  = tid >> 5;
    const int lane = tid & 31;
    const int wm   = (wid & 3) * 32;    // warp m offset (0..96)
    const int wn   = (wid >> 2) * 64;   // warp n offset (0,64)
    const int grp  = lane >> 2;         // 0..7
    const int qd   = lane & 3;          // 0..3

    const int bm = blockIdx.y * 128;
    const int bn = blockIdx.x * 128;
    const float* Ag = A  + (size_t)bm * K;
    const float* Bg = Bt + (size_t)bn * K;

    float acc[2][8][4];
    #pragma unroll
    for (int t = 0; t < 2; t++)
        #pragma unroll
        for (int n = 0; n < 8; n++)
            #pragma unroll
            for (int i = 0; i < 4; i++) acc[t][n][i] = 0.f;

    const int NC = K / KCH;   // 32

    auto load_stage = [&](int kc, int s) {
        const int koff = kc * KCH;
        const uint32_t sa = As_u + (uint32_t)s * OPER_W * 4;
        const uint32_t sb = Bs_u + (uint32_t)s * OPER_W * 4;
        #pragma unroll
        for (int i = 0; i < 4; i++) {
            int idx = tid + i * 256;       // 0..1023
            int r = idx >> 3, g = idx & 7; // 128 rows x 8 granules
            uint32_t so = (uint32_t)(r * PAD + g * 4) * 4;
            cp_async16(sa + so, Ag + (size_t)r * K + koff + g * 4);
            cp_async16(sb + so, Bg + (size_t)r * K + koff + g * 4);
        }
    };

    load_stage(0, 0);
    cp_commit();

    for (int kc = 0; kc < NC; kc++) {
        if (kc + 1 < NC) load_stage(kc + 1, (kc + 1) & 1);
        cp_commit();
        cp_wait<1>();
        __syncthreads();

        const float* as = As + (kc & 1) * OPER_W;
        const float* bs = Bs + (kc & 1) * OPER_W;

        #pragma unroll
        for (int k8 = 0; k8 < 4; k8++) {
            const int kk = k8 * 8;
            uint32_t af[2][4], bf[8][2];
            #pragma unroll
            for (int t = 0; t < 2; t++) {
                const float* ap = as + (wm + t*16 + grp) * PAD + kk;
                af[t][0] = f2tf32(ap[qd]);
                af[t][1] = f2tf32(ap[8*PAD + qd]);
                af[t][2] = f2tf32(ap[qd + 4]);
                af[t][3] = f2tf32(ap[8*PAD + qd + 4]);
            }
            #pragma unroll
            for (int n = 0; n < 8; n++) {
                const float* bp = bs + (wn + n*8 + grp) * PAD + kk;
                bf[n][0] = f2tf32(bp[qd]);
                bf[n][1] = f2tf32(bp[qd + 4]);
            }
            #pragma unroll
            for (int t = 0; t < 2; t++)
                #pragma unroll
                for (int n = 0; n < 8; n++)
                    mma_tf32(acc[t][n], af[t], bf[n]);
        }
        __syncthreads();
    }

    // Epilogue: c0 (r=grp, c=2qd), c1 (r, 2qd+1), c2 (r+8, 2qd), c3 (r+8, 2qd+1)
    #pragma unroll
    for (int t = 0; t < 2; t++) {
        const int r0 = bm + wm + t*16 + grp;
        #pragma unroll
        for (int n = 0; n < 8; n++) {
            const int col = bn + wn + n*8 + 2*qd;
            const float b0 = bias[col], b1 = bias[col + 1];
            float2 v0 = make_float2(acc[t][n][0] + b0, acc[t][n][1] + b1);
            float2 v1 = make_float2(acc[t][n][2] + b0, acc[t][n][3] + b1);
            *(float2*)(out + (size_t)r0 * N + col)       = v0;
            *(float2*)(out + (size_t)(r0 + 8) * N + col) = v1;
        }
    }
}

// ===========================================================================
// Causal flash attention, fp32, 2 q-rows per thread.
// grid = (T/128, H, B), block = 128 threads.
// Thread handles rows r0 = qt*128 + (tid>>1) and r1 = r0 + 64,
// dims [half*32, half*32+32). Each K/V shared read feeds both rows.
// ===========================================================================
__global__ void __launch_bounds__(128) attn_kernel(const float* __restrict__ qkv,
                                                   float* __restrict__ ao)
{
    const int qt  = blockIdx.x;     // 0..15
    const int h   = blockIdx.y;
    const int b   = blockIdx.z;
    const int tid = threadIdx.x;
    const int rw   = tid >> 1;      // 0..63
    const int half = tid & 1;
    const int r0 = qt*128 + rw;
    const int r1 = r0 + 64;

    __shared__ float ks[64][68];
    __shared__ float vs[64][68];

    const float scale = 0.125f;     // 1/sqrt(64)

    float q0[32], q1[32];
    {
        const float* qp0 = qkv + (size_t)(b*TT + r0)*3*CC + h*DD + half*32;
        const float* qp1 = qkv + (size_t)(b*TT + r1)*3*CC + h*DD + half*32;
        #pragma unroll
        for (int i = 0; i < 8; i++) {
            float4 f0 = *(const float4*)(qp0 + i*4);
            float4 f1 = *(const float4*)(qp1 + i*4);
            q0[i*4+0] = f0.x*scale; q0[i*4+1] = f0.y*scale;
            q0[i*4+2] = f0.z*scale; q0[i*4+3] = f0.w*scale;
            q1[i*4+0] = f1.x*scale; q1[i*4+1] = f1.y*scale;
            q1[i*4+2] = f1.z*scale; q1[i*4+3] = f1.w*scale;
        }
    }

    float acc0[32], acc1[32];
    #pragma unroll
    for (int i = 0; i < 32; i++) { acc0[i] = 0.f; acc1[i] = 0.f; }
    float m0 = -1e30f, l0 = 0.f, m1 = -1e30f, l1 = 0.f;

    const int ktmax = 2*qt + 1;
    for (int kt = 0; kt <= ktmax; kt++) {
        const float* kb = qkv + (size_t)(b*TT + kt*64)*3*CC + CC + h*DD;
        const float* vb = kb + CC;
        #pragma unroll
        for (int l = 0; l < 8; l++) {
            int idx = tid + l*128;
            int r = idx >> 4, c4 = idx & 15;
            *(float4*)&ks[r][c4*4] = *(const float4*)(kb + (size_t)r*3*CC + c4*4);
            *(float4*)&vs[r][c4*4] = *(const float4*)(vb + (size_t)r*3*CC + c4*4);
        }
        __syncthreads();

        const bool act0 = (kt <= 2*qt);          // uniform over block
        const bool d0   = (kt == 2*qt);
        const bool d1   = (kt == ktmax);

        #pragma unroll 2
        for (int kc = 0; kc < 64; kc += 8) {
            float s0[8], s1[8];
            #pragma unroll
            for (int j = 0; j < 8; j++) {
                const float4* kr = (const float4*)&ks[kc+j][half*32];
                float sum0 = 0.f, sum1 = 0.f;
                #pragma unroll
                for (int d4 = 0; d4 < 8; d4++) {
                    float4 k4 = kr[d4];
                    sum0 += q0[d4*4+0]*k4.x + q0[d4*4+1]*k4.y
                          + q0[d4*4+2]*k4.z + q0[d4*4+3]*k4.w;
                    sum1 += q1[d4*4+0]*k4.x + q1[d4*4+1]*k4.y
                          + q1[d4*4+2]*k4.z + q1[d4*4+3]*k4.w;
                }
                sum0 += __shfl_xor_sync(0xffffffffu, sum0, 1);
                sum1 += __shfl_xor_sync(0xffffffffu, sum1, 1);
                const int g = kt*64 + kc + j;
                if (d0 && g > r0) sum0 = -1e30f;
                if (d1 && g > r1) sum1 = -1e30f;
                s0[j] = sum0; s1[j] = sum1;
            }

            // row1 softmax state
            {
                float mn = m1;
                #pragma unroll
                for (int j = 0; j < 8; j++) mn = fmaxf(mn, s1[j]);
                float al = __expf(m1 - mn);
                m1 = mn; l1 *= al;
                #pragma unroll
                for (int d = 0; d < 32; d++) acc1[d] *= al;
            }
            // row0 softmax state
            if (act0) {
                float mn = m0;
                #pragma unroll
                for (int j = 0; j < 8; j++) mn = fmaxf(mn, s0[j]);
                float al = __expf(m0 - mn);
                m0 = mn; l0 *= al;
                #pragma unroll
                for (int d = 0; d < 32; d++) acc0[d] *= al;
            }

            #pragma unroll
            for (int j = 0; j < 8; j++) {
                float p1 = __expf(s1[j] - m1);
                l1 += p1;
                float p0 = 0.f;
                if (act0) { p0 = __expf(s0[j] - m0); l0 += p0; }
                const float4* vr = (const float4*)&vs[kc+j][half*32];
                #pragma unroll
                for (int d4 = 0; d4 < 8; d4++) {
                    float4 v4 = vr[d4];
                    acc1[d4*4+0] += p1*v4.x; acc1[d4*4+1] += p1*v4.y;
                    acc1[d4*4+2] += p1*v4.z; acc1[d4*4+3] += p1*v4.w;
                    acc0[d4*4+0] += p0*v4.x; acc0[d4*4+1] += p0*v4.y;
                    acc0[d4*4+2] += p0*v4.z; acc0[d4*4+3] += p0*v4.w;
                }
            }
        }
        __syncthreads();
    }

    const float inv0 = 1.f / l0;
    const float inv1 = 1.f / l1;
    float* op0 = ao + (size_t)(b*TT + r0)*CC + h*DD + half*32;
    float* op1 = ao + (size_t)(b*TT + r1)*CC + h*DD + half*32;
    #pragma unroll
    for (int i = 0; i < 8; i++) {
        float4 o0, o1;
        o0.x = acc0[i*4+0]*inv0; o0.y = acc0[i*4+1]*inv0;
        o0.z = acc0[i*4+2]*inv0; o0.w = acc0[i*4+3]*inv0;
        o1.x = acc1[i*4+0]*inv1; o1.y = acc1[i*4+1]*inv1;
        o1.z = acc1[i*4+2]*inv1; o1.w = acc1[i*4+3]*inv1;
        *(float4*)(op0 + i*4) = o0;
        *(float4*)(op1 + i*4) = o1;
    }
}

// ===========================================================================
extern "C" void kernel_launch(void* const* d_in, const int* in_sizes, int n_in,
                              void* d_out, int out_size)
{
    const float* x     = (const float*)d_in[0];
    const float* Wqkv  = (const float*)d_in[1];
    const float* bqkv  = (const float*)d_in[2];
    const float* Wproj = (const float*)d_in[3];
    const float* bproj = (const float*)d_in[4];
    float* out = (float*)d_out;

    float *qkv = nullptr, *ao = nullptr, *wt = nullptr, *wt2 = nullptr;
    cudaGetSymbolAddress((void**)&qkv, g_qkv);
    cudaGetSymbolAddress((void**)&ao,  g_ao);
    cudaGetSymbolAddress((void**)&wt,  g_wt);
    cudaGetSymbolAddress((void**)&wt2, g_wt2);

    static bool attr_set = false;
    if (!attr_set) {
        cudaFuncSetAttribute(gemm_mma, cudaFuncAttributeMaxDynamicSharedMemorySize,
                             SMEM_GEMM);
        attr_set = true;
    }

    // Transpose weights to [N, K]
    transpose_kernel<<<dim3(3*CC/32, CC/32), dim3(32, 8)>>>(Wqkv, wt, CC, 3*CC);
    transpose_kernel<<<dim3(CC/32,  CC/32), dim3(32, 8)>>>(Wproj, wt2, CC, CC);

    // 1) QKV projection: [4096,1024] @ [1024,3072] + bias
    gemm_mma<<<dim3(3*CC/128, MM/128), 256, SMEM_GEMM>>>(x, wt, bqkv, qkv,
                                                         MM, 3*CC, CC);
    // 2) Causal attention
    attn_kernel<<<dim3(TT/128, HH, BB), 128>>>(qkv, ao);

    // 3) Output projection: [4096,1024] @ [1024,1024] + bias
    gemm_mma<<<dim3(CC/128, MM/128), 256, SMEM_GEMM>>>(ao, wt2, bproj, out,
                                                       MM, CC, CC);
}

// round 6
// speedup vs baseline: 4.0215x; 2.3969x over previous
#include <cuda_runtime.h>
#include <math.h>
#include <cstdint>

#define BB 2
#define TT 2048
#define CC 1024
#define HH 16
#define DD 64
#define MM (BB*TT)   // 4096 rows

// Scratch (allocation-free: __device__ globals)
__device__ float g_qkv[(size_t)BB*TT*3*CC];  // [B,T,3C]
__device__ float g_ao [(size_t)BB*TT*CC];    // [B,T,C]
__device__ float g_wt [(size_t)3*CC*CC];     // W_qkv^T  [3C, C]
__device__ float g_wt2[(size_t)CC*CC];       // W_proj^T [C, C]

// ===========================================================================
// helpers (sm_80-era only: cp.async + mma.sync; no 'a'-gated instructions)
// ===========================================================================
__device__ __forceinline__ uint32_t smem_u32(const void* p) {
    uint32_t a;
    asm("{ .reg .u64 t; cvta.to.shared.u64 t, %1; cvt.u32.u64 %0, t; }"
        : "=r"(a) : "l"(p));
    return a;
}
__device__ __forceinline__ void cp_async16(uint32_t dst, const void* src) {
    asm volatile("cp.async.cg.shared.global [%0], [%1], 16;\n"
                 :: "r"(dst), "l"(src));
}
__device__ __forceinline__ void cp_commit() {
    asm volatile("cp.async.commit_group;\n" ::: "memory");
}
template<int N> __device__ __forceinline__ void cp_wait() {
    asm volatile("cp.async.wait_group %0;\n" :: "n"(N) : "memory");
}
__device__ __forceinline__ uint32_t f2tf32(float f) {
    uint32_t r;
    asm("cvt.rna.tf32.f32 %0, %1;" : "=r"(r) : "f"(f));
    return r;
}
__device__ __forceinline__ void mma_tf32(float c[4],
                                         const uint32_t a[4],
                                         const uint32_t b[2]) {
    asm volatile(
        "mma.sync.aligned.m16n8k8.row.col.f32.tf32.tf32.f32 "
        "{%0,%1,%2,%3}, {%4,%5,%6,%7}, {%8,%9}, {%0,%1,%2,%3};"
        : "+f"(c[0]), "+f"(c[1]), "+f"(c[2]), "+f"(c[3])
        : "r"(a[0]), "r"(a[1]), "r"(a[2]), "r"(a[3]),
          "r"(b[0]), "r"(b[1]));
}

// ===========================================================================
// Weight transpose: out[C,R] = in[R,C]^T
// ===========================================================================
__global__ void transpose_kernel(const float* __restrict__ in,
                                 float* __restrict__ out, int R, int C)
{
    __shared__ float t[32][33];
    int bx = blockIdx.x * 32, by = blockIdx.y * 32;
    #pragma unroll
    for (int i = 0; i < 32; i += 8)
        t[threadIdx.y + i][threadIdx.x] =
            in[(size_t)(by + threadIdx.y + i) * C + bx + threadIdx.x];
    __syncthreads();
    #pragma unroll
    for (int i = 0; i < 32; i += 8)
        out[(size_t)(bx + threadIdx.y + i) * R + by + threadIdx.x] =
            t[threadIdx.x][threadIdx.y + i];
}

// ===========================================================================
// tf32 mma.sync GEMM with bias: out[M,N] = A[M,K] @ Bt[N,K]^T + bias[N]
// (unchanged from R5 — passed at rel_err 3.15e-4)
// ===========================================================================
#define KCH 32
#define PAD 36
#define OPER_W (128*PAD)
#define SMEM_GEMM (4*OPER_W*4)

__global__ void __launch_bounds__(256) gemm_mma(const float* __restrict__ A,
                                                const float* __restrict__ Bt,
                                                const float* __restrict__ bias,
                                                float* __restrict__ out,
                                                int M, int N, int K)
{
    extern __shared__ float sm[];
    float* As = sm;
    float* Bs = sm + 2*OPER_W;
    const uint32_t As_u = smem_u32(As);
    const uint32_t Bs_u = smem_u32(Bs);

    const int tid  = threadIdx.x;
    const int wid  = tid >> 5;
    const int lane = tid & 31;
    const int wm   = (wid & 3) * 32;
    const int wn   = (wid >> 2) * 64;
    const int grp  = lane >> 2;
    const int qd   = lane & 3;

    const int bm = blockIdx.y * 128;
    const int bn = blockIdx.x * 128;
    const float* Ag = A  + (size_t)bm * K;
    const float* Bg = Bt + (size_t)bn * K;

    float acc[2][8][4];
    #pragma unroll
    for (int t = 0; t < 2; t++)
        #pragma unroll
        for (int n = 0; n < 8; n++)
            #pragma unroll
            for (int i = 0; i < 4; i++) acc[t][n][i] = 0.f;

    const int NC = K / KCH;

    auto load_stage = [&](int kc, int s) {
        const int koff = kc * KCH;
        const uint32_t sa = As_u + (uint32_t)s * OPER_W * 4;
        const uint32_t sb = Bs_u + (uint32_t)s * OPER_W * 4;
        #pragma unroll
        for (int i = 0; i < 4; i++) {
            int idx = tid + i * 256;
            int r = idx >> 3, g = idx & 7;
            uint32_t so = (uint32_t)(r * PAD + g * 4) * 4;
            cp_async16(sa + so, Ag + (size_t)r * K + koff + g * 4);
            cp_async16(sb + so, Bg + (size_t)r * K + koff + g * 4);
        }
    };

    load_stage(0, 0);
    cp_commit();

    for (int kc = 0; kc < NC; kc++) {
        if (kc + 1 < NC) load_stage(kc + 1, (kc + 1) & 1);
        cp_commit();
        cp_wait<1>();
        __syncthreads();

        const float* as = As + (kc & 1) * OPER_W;
        const float* bs = Bs + (kc & 1) * OPER_W;

        #pragma unroll
        for (int k8 = 0; k8 < 4; k8++) {
            const int kk = k8 * 8;
            uint32_t af[2][4], bf[8][2];
            #pragma unroll
            for (int t = 0; t < 2; t++) {
                const float* ap = as + (wm + t*16 + grp) * PAD + kk;
                af[t][0] = f2tf32(ap[qd]);
                af[t][1] = f2tf32(ap[8*PAD + qd]);
                af[t][2] = f2tf32(ap[qd + 4]);
                af[t][3] = f2tf32(ap[8*PAD + qd + 4]);
            }
            #pragma unroll
            for (int n = 0; n < 8; n++) {
                const float* bp = bs + (wn + n*8 + grp) * PAD + kk;
                bf[n][0] = f2tf32(bp[qd]);
                bf[n][1] = f2tf32(bp[qd + 4]);
            }
            #pragma unroll
            for (int t = 0; t < 2; t++)
                #pragma unroll
                for (int n = 0; n < 8; n++)
                    mma_tf32(acc[t][n], af[t], bf[n]);
        }
        __syncthreads();
    }

    #pragma unroll
    for (int t = 0; t < 2; t++) {
        const int r0 = bm + wm + t*16 + grp;
        #pragma unroll
        for (int n = 0; n < 8; n++) {
            const int col = bn + wn + n*8 + 2*qd;
            const float b0 = bias[col], b1 = bias[col + 1];
            float2 v0 = make_float2(acc[t][n][0] + b0, acc[t][n][1] + b1);
            float2 v1 = make_float2(acc[t][n][2] + b0, acc[t][n][3] + b1);
            *(float2*)(out + (size_t)r0 * N + col)       = v0;
            *(float2*)(out + (size_t)(r0 + 8) * N + col) = v1;
        }
    }
}

// ===========================================================================
// Tensor-core causal flash attention (tf32 mma.sync).
// grid = (T/128, H, B), block = 256 (8 warps). Warp w owns q-rows
// [qt*128 + 16w, +16). 64-key tiles, cp.async double buffer, fragment
// softmax, quad-shuffle P relayout for the PV mma.
// ===========================================================================
#define QS_PAD 68
#define KS_PAD 68
#define VS_PAD 72
#define QS_W (128*QS_PAD)
#define KS_W (64*KS_PAD)
#define VS_W (64*VS_PAD)
#define SMEM_ATTN ((QS_W + 2*KS_W + 2*VS_W)*4)

__global__ void __launch_bounds__(256) attn_mma(const float* __restrict__ qkv,
                                                float* __restrict__ ao)
{
    extern __shared__ float sm[];
    float* qs = sm;                    // [128][68]
    float* ks = sm + QS_W;             // [2][64][68]
    float* vs = ks + 2*KS_W;           // [2][64][72]
    const uint32_t ks_u = smem_u32(ks);
    const uint32_t vs_u = smem_u32(vs);

    const int qt = (int)gridDim.x - 1 - (int)blockIdx.x;  // heavy CTAs first
    const int h  = blockIdx.y;
    const int b  = blockIdx.z;
    const int tid  = threadIdx.x;
    const int wid  = tid >> 5;
    const int lane = tid & 31;
    const int grp  = lane >> 2;
    const int qd   = lane & 3;

    const int Q0   = qt * 128;
    const int rmin = Q0 + wid * 16;
    const int rmax = rmin + 15;
    const int row0 = rmin + grp;
    const int row1 = row0 + 8;

    // ---- stage Q tile (pre-scaled) ----
    const float scale = 0.125f;   // 1/sqrt(64)
    #pragma unroll
    for (int i = 0; i < 8; i++) {
        int idx = tid + i*256;
        int r = idx >> 4, c4 = idx & 15;
        float4 f = *(const float4*)(qkv + (size_t)(b*TT + Q0 + r)*3*CC
                                    + h*DD + c4*4);
        float* qp = qs + r*QS_PAD + c4*4;
        qp[0] = f.x*scale; qp[1] = f.y*scale; qp[2] = f.z*scale; qp[3] = f.w*scale;
    }
    __syncthreads();

    // ---- Q A-fragments (persistent, tf32) ----
    uint32_t aQ[8][4];
    {
        const float* qp = qs + (wid*16 + grp) * QS_PAD;
        #pragma unroll
        for (int k8 = 0; k8 < 8; k8++) {
            aQ[k8][0] = f2tf32(qp[8*k8 + qd]);
            aQ[k8][1] = f2tf32(qp[8*QS_PAD + 8*k8 + qd]);
            aQ[k8][2] = f2tf32(qp[8*k8 + qd + 4]);
            aQ[k8][3] = f2tf32(qp[8*QS_PAD + 8*k8 + qd + 4]);
        }
    }

    float o[8][4];
    #pragma unroll
    for (int n = 0; n < 8; n++)
        #pragma unroll
        for (int i = 0; i < 4; i++) o[n][i] = 0.f;
    float m0 = -1e30f, m1 = -1e30f, l0 = 0.f, l1 = 0.f;

    const int KT = 2*qt + 2;

    auto load_kv = [&](int kt, int s) {
        const float* kg = qkv + (size_t)(b*TT + kt*64)*3*CC + CC + h*DD;
        const float* vg = kg + CC;
        const uint32_t kb = ks_u + (uint32_t)s * KS_W * 4;
        const uint32_t vb = vs_u + (uint32_t)s * VS_W * 4;
        #pragma unroll
        for (int i = 0; i < 4; i++) {
            int idx = tid + i*256;
            int r = idx >> 4, c4 = idx & 15;
            cp_async16(kb + (uint32_t)(r*KS_PAD + c4*4)*4,
                       kg + (size_t)r*3*CC + c4*4);
            cp_async16(vb + (uint32_t)(r*VS_PAD + c4*4)*4,
                       vg + (size_t)r*3*CC + c4*4);
        }
    };

    load_kv(0, 0); cp_commit();
    load_kv(1, 1); cp_commit();

    for (int kt = 0; kt < KT; kt++) {
        if (kt + 1 < KT) cp_wait<1>(); else cp_wait<0>();
        __syncthreads();

        const float* kss = ks + (kt & 1) * KS_W;
        const float* vss = vs + (kt & 1) * VS_W;
        const int kb = kt * 64;

        if (kb <= rmax) {                       // warp-uniform visibility
            // ---- S = Q @ K^T ----
            float s[8][4];
            #pragma unroll
            for (int n = 0; n < 8; n++)
                #pragma unroll
                for (int i = 0; i < 4; i++) s[n][i] = 0.f;

            #pragma unroll
            for (int k8 = 0; k8 < 8; k8++) {
                #pragma unroll
                for (int n8 = 0; n8 < 8; n8++) {
                    const float* kp = kss + (8*n8 + grp)*KS_PAD + 8*k8;
                    uint32_t bk[2];
                    bk[0] = f2tf32(kp[qd]);
                    bk[1] = f2tf32(kp[qd + 4]);
                    mma_tf32(s[n8], aQ[k8], bk);
                }
            }

            // ---- causal mask (only on partial tiles) ----
            if (kb + 63 > rmin) {
                #pragma unroll
                for (int n8 = 0; n8 < 8; n8++) {
                    const int c0 = kb + 8*n8 + 2*qd;
                    if (c0     > row0) s[n8][0] = -1e30f;
                    if (c0 + 1 > row0) s[n8][1] = -1e30f;
                    if (c0     > row1) s[n8][2] = -1e30f;
                    if (c0 + 1 > row1) s[n8][3] = -1e30f;
                }
            }

            // ---- online softmax on fragments ----
            float mx0 = -1e30f, mx1 = -1e30f;
            #pragma unroll
            for (int n8 = 0; n8 < 8; n8++) {
                mx0 = fmaxf(mx0, fmaxf(s[n8][0], s[n8][1]));
                mx1 = fmaxf(mx1, fmaxf(s[n8][2], s[n8][3]));
            }
            mx0 = fmaxf(mx0, __shfl_xor_sync(0xffffffffu, mx0, 1));
            mx0 = fmaxf(mx0, __shfl_xor_sync(0xffffffffu, mx0, 2));
            mx1 = fmaxf(mx1, __shfl_xor_sync(0xffffffffu, mx1, 1));
            mx1 = fmaxf(mx1, __shfl_xor_sync(0xffffffffu, mx1, 2));

            const float mn0 = fmaxf(m0, mx0);
            const float mn1 = fmaxf(m1, mx1);
            const float al0 = __expf(m0 - mn0);
            const float al1 = __expf(m1 - mn1);
            m0 = mn0; m1 = mn1;
            l0 *= al0; l1 *= al1;
            #pragma unroll
            for (int n8 = 0; n8 < 8; n8++) {
                o[n8][0] *= al0; o[n8][1] *= al0;
                o[n8][2] *= al1; o[n8][3] *= al1;
            }
            #pragma unroll
            for (int n8 = 0; n8 < 8; n8++) {
                s[n8][0] = __expf(s[n8][0] - m0);
                s[n8][1] = __expf(s[n8][1] - m0);
                s[n8][2] = __expf(s[n8][2] - m1);
                s[n8][3] = __expf(s[n8][3] - m1);
                l0 += s[n8][0] + s[n8][1];
                l1 += s[n8][2] + s[n8][3];
            }

            // ---- O += P @ V  (P: C-layout -> A-layout via quad shuffles) ----
            const int srcA = (lane & ~3) | (qd >> 1);
            const int srcB = srcA + 2;
            const bool odd = (qd & 1);
            #pragma unroll
            for (int j = 0; j < 8; j++) {
                const float t00 = __shfl_sync(0xffffffffu, s[j][0], srcA);
                const float t01 = __shfl_sync(0xffffffffu, s[j][1], srcA);
                const float t10 = __shfl_sync(0xffffffffu, s[j][0], srcB);
                const float t11 = __shfl_sync(0xffffffffu, s[j][1], srcB);
                const float t20 = __shfl_sync(0xffffffffu, s[j][2], srcA);
                const float t21 = __shfl_sync(0xffffffffu, s[j][3], srcA);
                const float t30 = __shfl_sync(0xffffffffu, s[j][2], srcB);
                const float t31 = __shfl_sync(0xffffffffu, s[j][3], srcB);
                uint32_t ap[4];
                ap[0] = f2tf32(odd ? t01 : t00);
                ap[1] = f2tf32(odd ? t21 : t20);
                ap[2] = f2tf32(odd ? t11 : t10);
                ap[3] = f2tf32(odd ? t31 : t30);

                const float* vrow0 = vss + (8*j + qd) * VS_PAD;
                const float* vrow1 = vss + (8*j + qd + 4) * VS_PAD;
                #pragma unroll
                for (int n8 = 0; n8 < 8; n8++) {
                    uint32_t bv[2];
                    bv[0] = f2tf32(vrow0[8*n8 + grp]);
                    bv[1] = f2tf32(vrow1[8*n8 + grp]);
                    mma_tf32(o[n8], ap, bv);
                }
            }
        }

        __syncthreads();
        if (kt + 2 < KT) { load_kv(kt + 2, kt & 1); cp_commit(); }
    }

    // ---- finalize: row sums, normalize, write ----
    l0 += __shfl_xor_sync(0xffffffffu, l0, 1);
    l0 += __shfl_xor_sync(0xffffffffu, l0, 2);
    l1 += __shfl_xor_sync(0xffffffffu, l1, 1);
    l1 += __shfl_xor_sync(0xffffffffu, l1, 2);
    const float inv0 = 1.f / l0;
    const float inv1 = 1.f / l1;

    float* o0 = ao + (size_t)(b*TT + row0)*CC + h*DD;
    float* o1 = ao + (size_t)(b*TT + row1)*CC + h*DD;
    #pragma unroll
    for (int n8 = 0; n8 < 8; n8++) {
        const int col = 8*n8 + 2*qd;
        *(float2*)(o0 + col) = make_float2(o[n8][0]*inv0, o[n8][1]*inv0);
        *(float2*)(o1 + col) = make_float2(o[n8][2]*inv1, o[n8][3]*inv1);
    }
}

// ===========================================================================
extern "C" void kernel_launch(void* const* d_in, const int* in_sizes, int n_in,
                              void* d_out, int out_size)
{
    const float* x     = (const float*)d_in[0];
    const float* Wqkv  = (const float*)d_in[1];
    const float* bqkv  = (const float*)d_in[2];
    const float* Wproj = (const float*)d_in[3];
    const float* bproj = (const float*)d_in[4];
    float* out = (float*)d_out;

    float *qkv = nullptr, *ao = nullptr, *wt = nullptr, *wt2 = nullptr;
    cudaGetSymbolAddress((void**)&qkv, g_qkv);
    cudaGetSymbolAddress((void**)&ao,  g_ao);
    cudaGetSymbolAddress((void**)&wt,  g_wt);
    cudaGetSymbolAddress((void**)&wt2, g_wt2);

    static bool attr_set = false;
    if (!attr_set) {
        cudaFuncSetAttribute(gemm_mma, cudaFuncAttributeMaxDynamicSharedMemorySize,
                             SMEM_GEMM);
        cudaFuncSetAttribute(attn_mma, cudaFuncAttributeMaxDynamicSharedMemorySize,
                             SMEM_ATTN);
        attr_set = true;
    }

    // Transpose weights to [N, K]
    transpose_kernel<<<dim3(3*CC/32, CC/32), dim3(32, 8)>>>(Wqkv, wt, CC, 3*CC);
    transpose_kernel<<<dim3(CC/32,  CC/32), dim3(32, 8)>>>(Wproj, wt2, CC, CC);

    // 1) QKV projection
    gemm_mma<<<dim3(3*CC/128, MM/128), 256, SMEM_GEMM>>>(x, wt, bqkv, qkv,
                                                         MM, 3*CC, CC);
    // 2) Causal attention (tensor-core flash attention)
    attn_mma<<<dim3(TT/128, HH, BB), 256, SMEM_ATTN>>>(qkv, ao);

    // 3) Output projection
    gemm_mma<<<dim3(CC/128, MM/128), 256, SMEM_GEMM>>>(ao, wt2, bproj, out,
                                                       MM, CC, CC);
}

// round 7
// speedup vs baseline: 4.3053x; 1.0706x over previous
#include <cuda_runtime.h>
#include <math.h>
#include <cstdint>

#define BB 2
#define TT 2048
#define CC 1024
#define HH 16
#define DD 64
#define MM (BB*TT)   // 4096 rows

// Scratch (allocation-free: __device__ globals)
__device__ float g_qkv[(size_t)BB*TT*3*CC];  // [B,T,3C]
__device__ float g_ao [(size_t)BB*TT*CC];    // [B,T,C]
__device__ float g_wt [(size_t)3*CC*CC];     // W_qkv^T  [3C, C]
__device__ float g_wt2[(size_t)CC*CC];       // W_proj^T [C, C]

// ===========================================================================
// helpers (sm_80-era only: cp.async + mma.sync; no 'a'-gated instructions)
// ===========================================================================
__device__ __forceinline__ uint32_t smem_u32(const void* p) {
    uint32_t a;
    asm("{ .reg .u64 t; cvta.to.shared.u64 t, %1; cvt.u32.u64 %0, t; }"
        : "=r"(a) : "l"(p));
    return a;
}
__device__ __forceinline__ void cp_async16(uint32_t dst, const void* src) {
    asm volatile("cp.async.cg.shared.global [%0], [%1], 16;\n"
                 :: "r"(dst), "l"(src));
}
__device__ __forceinline__ void cp_commit() {
    asm volatile("cp.async.commit_group;\n" ::: "memory");
}
template<int N> __device__ __forceinline__ void cp_wait() {
    asm volatile("cp.async.wait_group %0;\n" :: "n"(N) : "memory");
}
__device__ __forceinline__ uint32_t f2tf32(float f) {
    uint32_t r;
    asm("cvt.rna.tf32.f32 %0, %1;" : "=r"(r) : "f"(f));
    return r;
}
__device__ __forceinline__ void mma_tf32(float c[4],
                                         const uint32_t a[4],
                                         const uint32_t b[2]) {
    asm volatile(
        "mma.sync.aligned.m16n8k8.row.col.f32.tf32.tf32.f32 "
        "{%0,%1,%2,%3}, {%4,%5,%6,%7}, {%8,%9}, {%0,%1,%2,%3};"
        : "+f"(c[0]), "+f"(c[1]), "+f"(c[2]), "+f"(c[3])
        : "r"(a[0]), "r"(a[1]), "r"(a[2]), "r"(a[3]),
          "r"(b[0]), "r"(b[1]));
}

// ===========================================================================
// Weight transpose: out[C,R] = in[R,C]^T
// ===========================================================================
__global__ void transpose_kernel(const float* __restrict__ in,
                                 float* __restrict__ out, int R, int C)
{
    __shared__ float t[32][33];
    int bx = blockIdx.x * 32, by = blockIdx.y * 32;
    #pragma unroll
    for (int i = 0; i < 32; i += 8)
        t[threadIdx.y + i][threadIdx.x] =
            in[(size_t)(by + threadIdx.y + i) * C + bx + threadIdx.x];
    __syncthreads();
    #pragma unroll
    for (int i = 0; i < 32; i += 8)
        out[(size_t)(bx + threadIdx.y + i) * R + by + threadIdx.x] =
            t[threadIdx.x][threadIdx.y + i];
}

// ===========================================================================
// tf32 mma.sync GEMM with bias: out[M,N] = A[M,K] @ Bt[N,K]^T + bias[N]
// (unchanged from R5 — passed at rel_err 3.15e-4)
// ===========================================================================
#define KCH 32
#define PAD 36
#define OPER_W (128*PAD)
#define SMEM_GEMM (4*OPER_W*4)

__global__ void __launch_bounds__(256) gemm_mma(const float* __restrict__ A,
                                                const float* __restrict__ Bt,
                                                const float* __restrict__ bias,
                                                float* __restrict__ out,
                                                int M, int N, int K)
{
    extern __shared__ float sm[];
    float* As = sm;
    float* Bs = sm + 2*OPER_W;
    const uint32_t As_u = smem_u32(As);
    const uint32_t Bs_u = smem_u32(Bs);

    const int tid  = threadIdx.x;
    const int wid  = tid >> 5;
    const int lane = tid & 31;
    const int wm   = (wid & 3) * 32;
    const int wn   = (wid >> 2) * 64;
    const int grp  = lane >> 2;
    const int qd   = lane & 3;

    const int bm = blockIdx.y * 128;
    const int bn = blockIdx.x * 128;
    const float* Ag = A  + (size_t)bm * K;
    const float* Bg = Bt + (size_t)bn * K;

    float acc[2][8][4];
    #pragma unroll
    for (int t = 0; t < 2; t++)
        #pragma unroll
        for (int n = 0; n < 8; n++)
            #pragma unroll
            for (int i = 0; i < 4; i++) acc[t][n][i] = 0.f;

    const int NC = K / KCH;

    auto load_stage = [&](int kc, int s) {
        const int koff = kc * KCH;
        const uint32_t sa = As_u + (uint32_t)s * OPER_W * 4;
        const uint32_t sb = Bs_u + (uint32_t)s * OPER_W * 4;
        #pragma unroll
        for (int i = 0; i < 4; i++) {
            int idx = tid + i * 256;
            int r = idx >> 3, g = idx & 7;
            uint32_t so = (uint32_t)(r * PAD + g * 4) * 4;
            cp_async16(sa + so, Ag + (size_t)r * K + koff + g * 4);
            cp_async16(sb + so, Bg + (size_t)r * K + koff + g * 4);
        }
    };

    load_stage(0, 0);
    cp_commit();

    for (int kc = 0; kc < NC; kc++) {
        if (kc + 1 < NC) load_stage(kc + 1, (kc + 1) & 1);
        cp_commit();
        cp_wait<1>();
        __syncthreads();

        const float* as = As + (kc & 1) * OPER_W;
        const float* bs = Bs + (kc & 1) * OPER_W;

        #pragma unroll
        for (int k8 = 0; k8 < 4; k8++) {
            const int kk = k8 * 8;
            uint32_t af[2][4], bf[8][2];
            #pragma unroll
            for (int t = 0; t < 2; t++) {
                const float* ap = as + (wm + t*16 + grp) * PAD + kk;
                af[t][0] = f2tf32(ap[qd]);
                af[t][1] = f2tf32(ap[8*PAD + qd]);
                af[t][2] = f2tf32(ap[qd + 4]);
                af[t][3] = f2tf32(ap[8*PAD + qd + 4]);
            }
            #pragma unroll
            for (int n = 0; n < 8; n++) {
                const float* bp = bs + (wn + n*8 + grp) * PAD + kk;
                bf[n][0] = f2tf32(bp[qd]);
                bf[n][1] = f2tf32(bp[qd + 4]);
            }
            #pragma unroll
            for (int t = 0; t < 2; t++)
                #pragma unroll
                for (int n = 0; n < 8; n++)
                    mma_tf32(acc[t][n], af[t], bf[n]);
        }
        __syncthreads();
    }

    #pragma unroll
    for (int t = 0; t < 2; t++) {
        const int r0 = bm + wm + t*16 + grp;
        #pragma unroll
        for (int n = 0; n < 8; n++) {
            const int col = bn + wn + n*8 + 2*qd;
            const float b0 = bias[col], b1 = bias[col + 1];
            float2 v0 = make_float2(acc[t][n][0] + b0, acc[t][n][1] + b1);
            float2 v1 = make_float2(acc[t][n][2] + b0, acc[t][n][3] + b1);
            *(float2*)(out + (size_t)r0 * N + col)       = v0;
            *(float2*)(out + (size_t)(r0 + 8) * N + col) = v1;
        }
    }
}

// ===========================================================================
// Tensor-core causal flash attention (tf32 mma.sync).
// grid = (T/128, H, B), block = 256 (8 warps), 2 CTAs/SM (reg-capped).
// Warp w owns q-rows [qt*128 + 16w, +16). Q fragments loaded directly from
// gmem (no smem stage). 64-key tiles, cp.async double buffer, fragment
// softmax, quad-shuffle P relayout for the PV mma.
// ===========================================================================
#define KS_PAD 68
#define VS_PAD 72
#define KS_W (64*KS_PAD)
#define VS_W (64*VS_PAD)
#define SMEM_ATTN ((2*KS_W + 2*VS_W)*4)

__global__ void __launch_bounds__(256, 2) attn_mma(const float* __restrict__ qkv,
                                                   float* __restrict__ ao)
{
    extern __shared__ float sm[];
    float* ks = sm;                    // [2][64][68]
    float* vs = sm + 2*KS_W;           // [2][64][72]
    const uint32_t ks_u = smem_u32(ks);
    const uint32_t vs_u = smem_u32(vs);

    const int qt = (int)gridDim.x - 1 - (int)blockIdx.x;  // heavy CTAs first
    const int h  = blockIdx.y;
    const int b  = blockIdx.z;
    const int tid  = threadIdx.x;
    const int wid  = tid >> 5;
    const int lane = tid & 31;
    const int grp  = lane >> 2;
    const int qd   = lane & 3;

    const int Q0   = qt * 128;
    const int rmin = Q0 + wid * 16;
    const int rmax = rmin + 15;
    const int row0 = rmin + grp;
    const int row1 = row0 + 8;

    // ---- Q A-fragments (persistent, tf32), loaded directly from gmem ----
    const float scale = 0.125f;   // 1/sqrt(64)
    uint32_t aQ[8][4];
    {
        const float* q0p = qkv + (size_t)(b*TT + row0)*3*CC + h*DD;
        const float* q1p = qkv + (size_t)(b*TT + row1)*3*CC + h*DD;
        #pragma unroll
        for (int k8 = 0; k8 < 8; k8++) {
            aQ[k8][0] = f2tf32(q0p[8*k8 + qd]     * scale);
            aQ[k8][1] = f2tf32(q1p[8*k8 + qd]     * scale);
            aQ[k8][2] = f2tf32(q0p[8*k8 + qd + 4] * scale);
            aQ[k8][3] = f2tf32(q1p[8*k8 + qd + 4] * scale);
        }
    }

    float o[8][4];
    #pragma unroll
    for (int n = 0; n < 8; n++)
        #pragma unroll
        for (int i = 0; i < 4; i++) o[n][i] = 0.f;
    float m0 = -1e30f, m1 = -1e30f, l0 = 0.f, l1 = 0.f;

    const int KT = 2*qt + 2;

    auto load_kv = [&](int kt, int s) {
        const float* kg = qkv + (size_t)(b*TT + kt*64)*3*CC + CC + h*DD;
        const float* vg = kg + CC;
        const uint32_t kb = ks_u + (uint32_t)s * KS_W * 4;
        const uint32_t vb = vs_u + (uint32_t)s * VS_W * 4;
        #pragma unroll
        for (int i = 0; i < 4; i++) {
            int idx = tid + i*256;
            int r = idx >> 4, c4 = idx & 15;
            cp_async16(kb + (uint32_t)(r*KS_PAD + c4*4)*4,
                       kg + (size_t)r*3*CC + c4*4);
            cp_async16(vb + (uint32_t)(r*VS_PAD + c4*4)*4,
                       vg + (size_t)r*3*CC + c4*4);
        }
    };

    load_kv(0, 0); cp_commit();
    load_kv(1, 1); cp_commit();

    for (int kt = 0; kt < KT; kt++) {
        if (kt + 1 < KT) cp_wait<1>(); else cp_wait<0>();
        __syncthreads();

        const float* kss = ks + (kt & 1) * KS_W;
        const float* vss = vs + (kt & 1) * VS_W;
        const int kb = kt * 64;

        if (kb <= rmax) {                       // warp-uniform visibility
            // ---- S = Q @ K^T ----
            float s[8][4];
            #pragma unroll
            for (int n = 0; n < 8; n++)
                #pragma unroll
                for (int i = 0; i < 4; i++) s[n][i] = 0.f;

            #pragma unroll
            for (int k8 = 0; k8 < 8; k8++) {
                #pragma unroll
                for (int n8 = 0; n8 < 8; n8++) {
                    const float* kp = kss + (8*n8 + grp)*KS_PAD + 8*k8;
                    uint32_t bk[2];
                    bk[0] = f2tf32(kp[qd]);
                    bk[1] = f2tf32(kp[qd + 4]);
                    mma_tf32(s[n8], aQ[k8], bk);
                }
            }

            // ---- causal mask (only on partial tiles) ----
            if (kb + 63 > rmin) {
                #pragma unroll
                for (int n8 = 0; n8 < 8; n8++) {
                    const int c0 = kb + 8*n8 + 2*qd;
                    if (c0     > row0) s[n8][0] = -1e30f;
                    if (c0 + 1 > row0) s[n8][1] = -1e30f;
                    if (c0     > row1) s[n8][2] = -1e30f;
                    if (c0 + 1 > row1) s[n8][3] = -1e30f;
                }
            }

            // ---- online softmax on fragments ----
            float mx0 = -1e30f, mx1 = -1e30f;
            #pragma unroll
            for (int n8 = 0; n8 < 8; n8++) {
                mx0 = fmaxf(mx0, fmaxf(s[n8][0], s[n8][1]));
                mx1 = fmaxf(mx1, fmaxf(s[n8][2], s[n8][3]));
            }
            mx0 = fmaxf(mx0, __shfl_xor_sync(0xffffffffu, mx0, 1));
            mx0 = fmaxf(mx0, __shfl_xor_sync(0xffffffffu, mx0, 2));
            mx1 = fmaxf(mx1, __shfl_xor_sync(0xffffffffu, mx1, 1));
            mx1 = fmaxf(mx1, __shfl_xor_sync(0xffffffffu, mx1, 2));

            const float mn0 = fmaxf(m0, mx0);
            const float mn1 = fmaxf(m1, mx1);
            const float al0 = __expf(m0 - mn0);
            const float al1 = __expf(m1 - mn1);
            m0 = mn0; m1 = mn1;
            l0 *= al0; l1 *= al1;
            #pragma unroll
            for (int n8 = 0; n8 < 8; n8++) {
                o[n8][0] *= al0; o[n8][1] *= al0;
                o[n8][2] *= al1; o[n8][3] *= al1;
            }
            #pragma unroll
            for (int n8 = 0; n8 < 8; n8++) {
                s[n8][0] = __expf(s[n8][0] - m0);
                s[n8][1] = __expf(s[n8][1] - m0);
                s[n8][2] = __expf(s[n8][2] - m1);
                s[n8][3] = __expf(s[n8][3] - m1);
                l0 += s[n8][0] + s[n8][1];
                l1 += s[n8][2] + s[n8][3];
            }

            // ---- O += P @ V  (P: C-layout -> A-layout via quad shuffles) ----
            const int srcA = (lane & ~3) | (qd >> 1);
            const int srcB = srcA + 2;
            const bool odd = (qd & 1);
            #pragma unroll
            for (int j = 0; j < 8; j++) {
                const float t00 = __shfl_sync(0xffffffffu, s[j][0], srcA);
                const float t01 = __shfl_sync(0xffffffffu, s[j][1], srcA);
                const float t10 = __shfl_sync(0xffffffffu, s[j][0], srcB);
                const float t11 = __shfl_sync(0xffffffffu, s[j][1], srcB);
                const float t20 = __shfl_sync(0xffffffffu, s[j][2], srcA);
                const float t21 = __shfl_sync(0xffffffffu, s[j][3], srcA);
                const float t30 = __shfl_sync(0xffffffffu, s[j][2], srcB);
                const float t31 = __shfl_sync(0xffffffffu, s[j][3], srcB);
                uint32_t ap[4];
                ap[0] = f2tf32(odd ? t01 : t00);
                ap[1] = f2tf32(odd ? t21 : t20);
                ap[2] = f2tf32(odd ? t11 : t10);
                ap[3] = f2tf32(odd ? t31 : t30);

                const float* vrow0 = vss + (8*j + qd) * VS_PAD;
                const float* vrow1 = vss + (8*j + qd + 4) * VS_PAD;
                #pragma unroll
                for (int n8 = 0; n8 < 8; n8++) {
                    uint32_t bv[2];
                    bv[0] = f2tf32(vrow0[8*n8 + grp]);
                    bv[1] = f2tf32(vrow1[8*n8 + grp]);
                    mma_tf32(o[n8], ap, bv);
                }
            }
        }

        __syncthreads();
        if (kt + 2 < KT) { load_kv(kt + 2, kt & 1); cp_commit(); }
    }

    // ---- finalize: row sums, normalize, write ----
    l0 += __shfl_xor_sync(0xffffffffu, l0, 1);
    l0 += __shfl_xor_sync(0xffffffffu, l0, 2);
    l1 += __shfl_xor_sync(0xffffffffu, l1, 1);
    l1 += __shfl_xor_sync(0xffffffffu, l1, 2);
    const float inv0 = 1.f / l0;
    const float inv1 = 1.f / l1;

    float* o0 = ao + (size_t)(b*TT + row0)*CC + h*DD;
    float* o1 = ao + (size_t)(b*TT + row1)*CC + h*DD;
    #pragma unroll
    for (int n8 = 0; n8 < 8; n8++) {
        const int col = 8*n8 + 2*qd;
        *(float2*)(o0 + col) = make_float2(o[n8][0]*inv0, o[n8][1]*inv0);
        *(float2*)(o1 + col) = make_float2(o[n8][2]*inv1, o[n8][3]*inv1);
    }
}

// ===========================================================================
extern "C" void kernel_launch(void* const* d_in, const int* in_sizes, int n_in,
                              void* d_out, int out_size)
{
    const float* x     = (const float*)d_in[0];
    const float* Wqkv  = (const float*)d_in[1];
    const float* bqkv  = (const float*)d_in[2];
    const float* Wproj = (const float*)d_in[3];
    const float* bproj = (const float*)d_in[4];
    float* out = (float*)d_out;

    float *qkv = nullptr, *ao = nullptr, *wt = nullptr, *wt2 = nullptr;
    cudaGetSymbolAddress((void**)&qkv, g_qkv);
    cudaGetSymbolAddress((void**)&ao,  g_ao);
    cudaGetSymbolAddress((void**)&wt,  g_wt);
    cudaGetSymbolAddress((void**)&wt2, g_wt2);

    static bool attr_set = false;
    if (!attr_set) {
        cudaFuncSetAttribute(gemm_mma, cudaFuncAttributeMaxDynamicSharedMemorySize,
                             SMEM_GEMM);
        cudaFuncSetAttribute(attn_mma, cudaFuncAttributeMaxDynamicSharedMemorySize,
                             SMEM_ATTN);
        attr_set = true;
    }

    // Transpose weights to [N, K]
    transpose_kernel<<<dim3(3*CC/32, CC/32), dim3(32, 8)>>>(Wqkv, wt, CC, 3*CC);
    transpose_kernel<<<dim3(CC/32,  CC/32), dim3(32, 8)>>>(Wproj, wt2, CC, CC);

    // 1) QKV projection
    gemm_mma<<<dim3(3*CC/128, MM/128), 256, SMEM_GEMM>>>(x, wt, bqkv, qkv,
                                                         MM, 3*CC, CC);
    // 2) Causal attention (tensor-core flash attention)
    attn_mma<<<dim3(TT/128, HH, BB), 256, SMEM_ATTN>>>(qkv, ao);

    // 3) Output projection
    gemm_mma<<<dim3(CC/128, MM/128), 256, SMEM_GEMM>>>(ao, wt2, bproj, out,
                                                       MM, CC, CC);
}

// round 8
// speedup vs baseline: 4.5061x; 1.0466x over previous
#include <cuda_runtime.h>
#include <math.h>
#include <cstdint>

#define BB 2
#define TT 2048
#define CC 1024
#define HH 16
#define DD 64
#define MM (BB*TT)   // 4096 rows

// Scratch (allocation-free: __device__ globals)
__device__ float g_qkv[(size_t)BB*TT*3*CC];  // [B,T,3C]  (tf32-rounded)
__device__ float g_ao [(size_t)BB*TT*CC];    // [B,T,C]   (tf32-rounded)
__device__ float g_wt [(size_t)3*CC*CC];     // W_qkv^T   (tf32-rounded)
__device__ float g_wt2[(size_t)CC*CC];       // W_proj^T  (tf32-rounded)
__device__ float g_xr [(size_t)MM*CC];       // x         (tf32-rounded)

// ===========================================================================
// helpers (sm_80-era only: cp.async + mma.sync; no 'a'-gated instructions)
// ===========================================================================
__device__ __forceinline__ uint32_t smem_u32(const void* p) {
    uint32_t a;
    asm("{ .reg .u64 t; cvta.to.shared.u64 t, %1; cvt.u32.u64 %0, t; }"
        : "=r"(a) : "l"(p));
    return a;
}
__device__ __forceinline__ void cp_async16(uint32_t dst, const void* src) {
    asm volatile("cp.async.cg.shared.global [%0], [%1], 16;\n"
                 :: "r"(dst), "l"(src));
}
__device__ __forceinline__ void cp_commit() {
    asm volatile("cp.async.commit_group;\n" ::: "memory");
}
template<int N> __device__ __forceinline__ void cp_wait() {
    asm volatile("cp.async.wait_group %0;\n" :: "n"(N) : "memory");
}
__device__ __forceinline__ uint32_t f2tf32(float f) {
    uint32_t r;
    asm("cvt.rna.tf32.f32 %0, %1;" : "=r"(r) : "f"(f));
    return r;
}
__device__ __forceinline__ float rnd_tf32(float f) {
    return __uint_as_float(f2tf32(f));
}
__device__ __forceinline__ void mma_tf32(float c[4],
                                         const uint32_t a[4],
                                         const uint32_t b[2]) {
    asm volatile(
        "mma.sync.aligned.m16n8k8.row.col.f32.tf32.tf32.f32 "
        "{%0,%1,%2,%3}, {%4,%5,%6,%7}, {%8,%9}, {%0,%1,%2,%3};"
        : "+f"(c[0]), "+f"(c[1]), "+f"(c[2]), "+f"(c[3])
        : "r"(a[0]), "r"(a[1]), "r"(a[2]), "r"(a[3]),
          "r"(b[0]), "r"(b[1]));
}

// ===========================================================================
// Elementwise tf32 rounding: out[i] = rna_tf32(in[i])  (n % 4 == 0)
// ===========================================================================
__global__ void round_kernel(const float* __restrict__ in,
                             float* __restrict__ out, int n)
{
    int i = (blockIdx.x * blockDim.x + threadIdx.x) * 4;
    if (i < n) {
        float4 f = *(const float4*)(in + i);
        f.x = rnd_tf32(f.x); f.y = rnd_tf32(f.y);
        f.z = rnd_tf32(f.z); f.w = rnd_tf32(f.w);
        *(float4*)(out + i) = f;
    }
}

// ===========================================================================
// Weight transpose + tf32 rounding: out[C,R] = rna_tf32(in[R,C]^T)
// ===========================================================================
__global__ void transpose_kernel(const float* __restrict__ in,
                                 float* __restrict__ out, int R, int C)
{
    __shared__ float t[32][33];
    int bx = blockIdx.x * 32, by = blockIdx.y * 32;
    #pragma unroll
    for (int i = 0; i < 32; i += 8)
        t[threadIdx.y + i][threadIdx.x] =
            in[(size_t)(by + threadIdx.y + i) * C + bx + threadIdx.x];
    __syncthreads();
    #pragma unroll
    for (int i = 0; i < 32; i += 8)
        out[(size_t)(bx + threadIdx.y + i) * R + by + threadIdx.x] =
            rnd_tf32(t[threadIdx.x][threadIdx.y + i]);
}

// ===========================================================================
// tf32 mma.sync GEMM with bias: out[M,N] = A[M,K] @ Bt[N,K]^T + bias[N]
// A and Bt MUST be pre-rounded to tf32 bit patterns (raw-bit fragments).
// RND: round output to tf32 (for tensors consumed by later mma stages).
// ===========================================================================
#define KCH 32
#define PAD 36
#define OPER_W (128*PAD)
#define SMEM_GEMM (4*OPER_W*4)

template<bool RND>
__global__ void __launch_bounds__(256) gemm_mma(const float* __restrict__ A,
                                                const float* __restrict__ Bt,
                                                const float* __restrict__ bias,
                                                float* __restrict__ out,
                                                int M, int N, int K)
{
    extern __shared__ float sm[];
    float* As = sm;
    float* Bs = sm + 2*OPER_W;
    const uint32_t As_u = smem_u32(As);
    const uint32_t Bs_u = smem_u32(Bs);

    const int tid  = threadIdx.x;
    const int wid  = tid >> 5;
    const int lane = tid & 31;
    const int wm   = (wid & 3) * 32;
    const int wn   = (wid >> 2) * 64;
    const int grp  = lane >> 2;
    const int qd   = lane & 3;

    const int bm = blockIdx.y * 128;
    const int bn = blockIdx.x * 128;
    const float* Ag = A  + (size_t)bm * K;
    const float* Bg = Bt + (size_t)bn * K;

    float acc[2][8][4];
    #pragma unroll
    for (int t = 0; t < 2; t++)
        #pragma unroll
        for (int n = 0; n < 8; n++)
            #pragma unroll
            for (int i = 0; i < 4; i++) acc[t][n][i] = 0.f;

    const int NC = K / KCH;

    auto load_stage = [&](int kc, int s) {
        const int koff = kc * KCH;
        const uint32_t sa = As_u + (uint32_t)s * OPER_W * 4;
        const uint32_t sb = Bs_u + (uint32_t)s * OPER_W * 4;
        #pragma unroll
        for (int i = 0; i < 4; i++) {
            int idx = tid + i * 256;
            int r = idx >> 3, g = idx & 7;
            uint32_t so = (uint32_t)(r * PAD + g * 4) * 4;
            cp_async16(sa + so, Ag + (size_t)r * K + koff + g * 4);
            cp_async16(sb + so, Bg + (size_t)r * K + koff + g * 4);
        }
    };

    load_stage(0, 0);
    cp_commit();

    for (int kc = 0; kc < NC; kc++) {
        if (kc + 1 < NC) load_stage(kc + 1, (kc + 1) & 1);
        cp_commit();
        cp_wait<1>();
        __syncthreads();

        const float* as = As + (kc & 1) * OPER_W;
        const float* bs = Bs + (kc & 1) * OPER_W;

        #pragma unroll
        for (int k8 = 0; k8 < 4; k8++) {
            const int kk = k8 * 8;
            uint32_t af[2][4], bf[8][2];
            #pragma unroll
            for (int t = 0; t < 2; t++) {
                const float* ap = as + (wm + t*16 + grp) * PAD + kk;
                af[t][0] = __float_as_uint(ap[qd]);
                af[t][1] = __float_as_uint(ap[8*PAD + qd]);
                af[t][2] = __float_as_uint(ap[qd + 4]);
                af[t][3] = __float_as_uint(ap[8*PAD + qd + 4]);
            }
            #pragma unroll
            for (int n = 0; n < 8; n++) {
                const float* bp = bs + (wn + n*8 + grp) * PAD + kk;
                bf[n][0] = __float_as_uint(bp[qd]);
                bf[n][1] = __float_as_uint(bp[qd + 4]);
            }
            #pragma unroll
            for (int t = 0; t < 2; t++)
                #pragma unroll
                for (int n = 0; n < 8; n++)
                    mma_tf32(acc[t][n], af[t], bf[n]);
        }
        __syncthreads();
    }

    #pragma unroll
    for (int t = 0; t < 2; t++) {
        const int r0 = bm + wm + t*16 + grp;
        #pragma unroll
        for (int n = 0; n < 8; n++) {
            const int col = bn + wn + n*8 + 2*qd;
            const float b0 = bias[col], b1 = bias[col + 1];
            float v00 = acc[t][n][0] + b0, v01 = acc[t][n][1] + b1;
            float v10 = acc[t][n][2] + b0, v11 = acc[t][n][3] + b1;
            if (RND) {
                v00 = rnd_tf32(v00); v01 = rnd_tf32(v01);
                v10 = rnd_tf32(v10); v11 = rnd_tf32(v11);
            }
            *(float2*)(out + (size_t)r0 * N + col)       = make_float2(v00, v01);
            *(float2*)(out + (size_t)(r0 + 8) * N + col) = make_float2(v10, v11);
        }
    }
}

// ===========================================================================
// Tensor-core causal flash attention (tf32 mma.sync).
// qkv is pre-rounded to tf32 bit patterns -> K/V/Q fragments are raw bits
// (no cvt in the inner loop). Output written tf32-rounded for the proj GEMM.
// grid = (T/128, H, B), block = 256 (8 warps), 2 CTAs/SM.
// ===========================================================================
#define KS_PAD 68
#define VS_PAD 72
#define KS_W (64*KS_PAD)
#define VS_W (64*VS_PAD)
#define SMEM_ATTN ((2*KS_W + 2*VS_W)*4)

__global__ void __launch_bounds__(256, 2) attn_mma(const float* __restrict__ qkv,
                                                   float* __restrict__ ao)
{
    extern __shared__ float sm[];
    float* ks = sm;                    // [2][64][68]
    float* vs = sm + 2*KS_W;           // [2][64][72]
    const uint32_t ks_u = smem_u32(ks);
    const uint32_t vs_u = smem_u32(vs);

    const int qt = (int)gridDim.x - 1 - (int)blockIdx.x;  // heavy CTAs first
    const int h  = blockIdx.y;
    const int b  = blockIdx.z;
    const int tid  = threadIdx.x;
    const int wid  = tid >> 5;
    const int lane = tid & 31;
    const int grp  = lane >> 2;
    const int qd   = lane & 3;

    const int Q0   = qt * 128;
    const int rmin = Q0 + wid * 16;
    const int rmax = rmin + 15;
    const int row0 = rmin + grp;
    const int row1 = row0 + 8;

    // ---- Q A-fragments: pre-rounded data; *0.125 (2^-3) is exact on tf32 ----
    const float scale = 0.125f;
    uint32_t aQ[8][4];
    {
        const float* q0p = qkv + (size_t)(b*TT + row0)*3*CC + h*DD;
        const float* q1p = qkv + (size_t)(b*TT + row1)*3*CC + h*DD;
        #pragma unroll
        for (int k8 = 0; k8 < 8; k8++) {
            aQ[k8][0] = __float_as_uint(q0p[8*k8 + qd]     * scale);
            aQ[k8][1] = __float_as_uint(q1p[8*k8 + qd]     * scale);
            aQ[k8][2] = __float_as_uint(q0p[8*k8 + qd + 4] * scale);
            aQ[k8][3] = __float_as_uint(q1p[8*k8 + qd + 4] * scale);
        }
    }

    float o[8][4];
    #pragma unroll
    for (int n = 0; n < 8; n++)
        #pragma unroll
        for (int i = 0; i < 4; i++) o[n][i] = 0.f;
    float m0 = -1e30f, m1 = -1e30f, l0 = 0.f, l1 = 0.f;

    const int KT = 2*qt + 2;

    auto load_kv = [&](int kt, int s) {
        const float* kg = qkv + (size_t)(b*TT + kt*64)*3*CC + CC + h*DD;
        const float* vg = kg + CC;
        const uint32_t kb = ks_u + (uint32_t)s * KS_W * 4;
        const uint32_t vb = vs_u + (uint32_t)s * VS_W * 4;
        #pragma unroll
        for (int i = 0; i < 4; i++) {
            int idx = tid + i*256;
            int r = idx >> 4, c4 = idx & 15;
            cp_async16(kb + (uint32_t)(r*KS_PAD + c4*4)*4,
                       kg + (size_t)r*3*CC + c4*4);
            cp_async16(vb + (uint32_t)(r*VS_PAD + c4*4)*4,
                       vg + (size_t)r*3*CC + c4*4);
        }
    };

    load_kv(0, 0); cp_commit();
    load_kv(1, 1); cp_commit();

    for (int kt = 0; kt < KT; kt++) {
        if (kt + 1 < KT) cp_wait<1>(); else cp_wait<0>();
        __syncthreads();

        const float* kss = ks + (kt & 1) * KS_W;
        const float* vss = vs + (kt & 1) * VS_W;
        const int kb = kt * 64;

        if (kb <= rmax) {                       // warp-uniform visibility
            // ---- S = Q @ K^T (raw-bit B fragments) ----
            float s[8][4];
            #pragma unroll
            for (int n = 0; n < 8; n++)
                #pragma unroll
                for (int i = 0; i < 4; i++) s[n][i] = 0.f;

            #pragma unroll
            for (int k8 = 0; k8 < 8; k8++) {
                #pragma unroll
                for (int n8 = 0; n8 < 8; n8++) {
                    const float* kp = kss + (8*n8 + grp)*KS_PAD + 8*k8;
                    uint32_t bk[2];
                    bk[0] = __float_as_uint(kp[qd]);
                    bk[1] = __float_as_uint(kp[qd + 4]);
                    mma_tf32(s[n8], aQ[k8], bk);
                }
            }

            // ---- causal mask (only on partial tiles) ----
            if (kb + 63 > rmin) {
                #pragma unroll
                for (int n8 = 0; n8 < 8; n8++) {
                    const int c0 = kb + 8*n8 + 2*qd;
                    if (c0     > row0) s[n8][0] = -1e30f;
                    if (c0 + 1 > row0) s[n8][1] = -1e30f;
                    if (c0     > row1) s[n8][2] = -1e30f;
                    if (c0 + 1 > row1) s[n8][3] = -1e30f;
                }
            }

            // ---- online softmax on fragments ----
            float mx0 = -1e30f, mx1 = -1e30f;
            #pragma unroll
            for (int n8 = 0; n8 < 8; n8++) {
                mx0 = fmaxf(mx0, fmaxf(s[n8][0], s[n8][1]));
                mx1 = fmaxf(mx1, fmaxf(s[n8][2], s[n8][3]));
            }
            mx0 = fmaxf(mx0, __shfl_xor_sync(0xffffffffu, mx0, 1));
            mx0 = fmaxf(mx0, __shfl_xor_sync(0xffffffffu, mx0, 2));
            mx1 = fmaxf(mx1, __shfl_xor_sync(0xffffffffu, mx1, 1));
            mx1 = fmaxf(mx1, __shfl_xor_sync(0xffffffffu, mx1, 2));

            const float mn0 = fmaxf(m0, mx0);
            const float mn1 = fmaxf(m1, mx1);
            const float al0 = __expf(m0 - mn0);
            const float al1 = __expf(m1 - mn1);
            m0 = mn0; m1 = mn1;
            l0 *= al0; l1 *= al1;
            #pragma unroll
            for (int n8 = 0; n8 < 8; n8++) {
                o[n8][0] *= al0; o[n8][1] *= al0;
                o[n8][2] *= al1; o[n8][3] *= al1;
            }
            #pragma unroll
            for (int n8 = 0; n8 < 8; n8++) {
                s[n8][0] = __expf(s[n8][0] - m0);
                s[n8][1] = __expf(s[n8][1] - m0);
                s[n8][2] = __expf(s[n8][2] - m1);
                s[n8][3] = __expf(s[n8][3] - m1);
                l0 += s[n8][0] + s[n8][1];
                l1 += s[n8][2] + s[n8][3];
            }

            // ---- O += P @ V  (P: C-layout -> A-layout via quad shuffles) ----
            const int srcA = (lane & ~3) | (qd >> 1);
            const int srcB = srcA + 2;
            const bool odd = (qd & 1);
            #pragma unroll
            for (int j = 0; j < 8; j++) {
                const float t00 = __shfl_sync(0xffffffffu, s[j][0], srcA);
                const float t01 = __shfl_sync(0xffffffffu, s[j][1], srcA);
                const float t10 = __shfl_sync(0xffffffffu, s[j][0], srcB);
                const float t11 = __shfl_sync(0xffffffffu, s[j][1], srcB);
                const float t20 = __shfl_sync(0xffffffffu, s[j][2], srcA);
                const float t21 = __shfl_sync(0xffffffffu, s[j][3], srcA);
                const float t30 = __shfl_sync(0xffffffffu, s[j][2], srcB);
                const float t31 = __shfl_sync(0xffffffffu, s[j][3], srcB);
                uint32_t ap[4];
                ap[0] = f2tf32(odd ? t01 : t00);
                ap[1] = f2tf32(odd ? t21 : t20);
                ap[2] = f2tf32(odd ? t11 : t10);
                ap[3] = f2tf32(odd ? t31 : t30);

                const float* vrow0 = vss + (8*j + qd) * VS_PAD;
                const float* vrow1 = vss + (8*j + qd + 4) * VS_PAD;
                #pragma unroll
                for (int n8 = 0; n8 < 8; n8++) {
                    uint32_t bv[2];
                    bv[0] = __float_as_uint(vrow0[8*n8 + grp]);
                    bv[1] = __float_as_uint(vrow1[8*n8 + grp]);
                    mma_tf32(o[n8], ap, bv);
                }
            }
        }

        __syncthreads();
        if (kt + 2 < KT) { load_kv(kt + 2, kt & 1); cp_commit(); }
    }

    // ---- finalize: row sums, normalize, write (tf32-rounded for proj) ----
    l0 += __shfl_xor_sync(0xffffffffu, l0, 1);
    l0 += __shfl_xor_sync(0xffffffffu, l0, 2);
    l1 += __shfl_xor_sync(0xffffffffu, l1, 1);
    l1 += __shfl_xor_sync(0xffffffffu, l1, 2);
    const float inv0 = 1.f / l0;
    const float inv1 = 1.f / l1;

    float* o0 = ao + (size_t)(b*TT + row0)*CC + h*DD;
    float* o1 = ao + (size_t)(b*TT + row1)*CC + h*DD;
    #pragma unroll
    for (int n8 = 0; n8 < 8; n8++) {
        const int col = 8*n8 + 2*qd;
        *(float2*)(o0 + col) = make_float2(rnd_tf32(o[n8][0]*inv0),
                                           rnd_tf32(o[n8][1]*inv0));
        *(float2*)(o1 + col) = make_float2(rnd_tf32(o[n8][2]*inv1),
                                           rnd_tf32(o[n8][3]*inv1));
    }
}

// ===========================================================================
extern "C" void kernel_launch(void* const* d_in, const int* in_sizes, int n_in,
                              void* d_out, int out_size)
{
    const float* x     = (const float*)d_in[0];
    const float* Wqkv  = (const float*)d_in[1];
    const float* bqkv  = (const float*)d_in[2];
    const float* Wproj = (const float*)d_in[3];
    const float* bproj = (const float*)d_in[4];
    float* out = (float*)d_out;

    float *qkv = nullptr, *ao = nullptr, *wt = nullptr, *wt2 = nullptr, *xr = nullptr;
    cudaGetSymbolAddress((void**)&qkv, g_qkv);
    cudaGetSymbolAddress((void**)&ao,  g_ao);
    cudaGetSymbolAddress((void**)&wt,  g_wt);
    cudaGetSymbolAddress((void**)&wt2, g_wt2);
    cudaGetSymbolAddress((void**)&xr,  g_xr);

    static bool attr_set = false;
    if (!attr_set) {
        cudaFuncSetAttribute(gemm_mma<true>,
                             cudaFuncAttributeMaxDynamicSharedMemorySize, SMEM_GEMM);
        cudaFuncSetAttribute(gemm_mma<false>,
                             cudaFuncAttributeMaxDynamicSharedMemorySize, SMEM_GEMM);
        cudaFuncSetAttribute(attn_mma,
                             cudaFuncAttributeMaxDynamicSharedMemorySize, SMEM_ATTN);
        attr_set = true;
    }

    // Pre-round x; transpose+round weights
    round_kernel<<<(MM*CC/4 + 255)/256, 256>>>(x, xr, MM*CC);
    transpose_kernel<<<dim3(3*CC/32, CC/32), dim3(32, 8)>>>(Wqkv, wt, CC, 3*CC);
    transpose_kernel<<<dim3(CC/32,  CC/32), dim3(32, 8)>>>(Wproj, wt2, CC, CC);

    // 1) QKV projection (output rounded to tf32 for attention)
    gemm_mma<true><<<dim3(3*CC/128, MM/128), 256, SMEM_GEMM>>>(xr, wt, bqkv, qkv,
                                                               MM, 3*CC, CC);
    // 2) Causal attention (tensor-core flash attention, raw-bit fragments)
    attn_mma<<<dim3(TT/128, HH, BB), 256, SMEM_ATTN>>>(qkv, ao);

    // 3) Output projection (final output stays fp32)
    gemm_mma<false><<<dim3(CC/128, MM/128), 256, SMEM_GEMM>>>(ao, wt2, bproj, out,
                                                              MM, CC, CC);
}

// round 9
// speedup vs baseline: 4.7473x; 1.0535x over previous
#include <cuda_runtime.h>
#include <math.h>
#include <cstdint>

#define BB 2
#define TT 2048
#define CC 1024
#define HH 16
#define DD 64
#define MM (BB*TT)   // 4096 rows

// Scratch (allocation-free: __device__ globals)
__device__ float g_qkv[(size_t)BB*TT*3*CC];  // [B,T,3C]  (tf32-rounded)
__device__ float g_ao [(size_t)BB*TT*CC];    // [B,T,C]   (tf32-rounded)
__device__ float g_wt [(size_t)3*CC*CC];     // W_qkv^T   (tf32-rounded)
__device__ float g_wt2[(size_t)CC*CC];       // W_proj^T  (tf32-rounded)
__device__ float g_xr [(size_t)MM*CC];       // x         (tf32-rounded)

// ===========================================================================
// helpers (sm_80-era only: cp.async + mma.sync; no 'a'-gated instructions)
// ===========================================================================
__device__ __forceinline__ uint32_t smem_u32(const void* p) {
    uint32_t a;
    asm("{ .reg .u64 t; cvta.to.shared.u64 t, %1; cvt.u32.u64 %0, t; }"
        : "=r"(a) : "l"(p));
    return a;
}
__device__ __forceinline__ void cp_async16(uint32_t dst, const void* src) {
    asm volatile("cp.async.cg.shared.global [%0], [%1], 16;\n"
                 :: "r"(dst), "l"(src));
}
__device__ __forceinline__ void cp_commit() {
    asm volatile("cp.async.commit_group;\n" ::: "memory");
}
template<int N> __device__ __forceinline__ void cp_wait() {
    asm volatile("cp.async.wait_group %0;\n" :: "n"(N) : "memory");
}
__device__ __forceinline__ uint32_t f2tf32(float f) {
    uint32_t r;
    asm("cvt.rna.tf32.f32 %0, %1;" : "=r"(r) : "f"(f));
    return r;
}
__device__ __forceinline__ float rnd_tf32(float f) {
    return __uint_as_float(f2tf32(f));
}
__device__ __forceinline__ void mma_tf32(float c[4],
                                         const uint32_t a[4],
                                         const uint32_t b[2]) {
    asm volatile(
        "mma.sync.aligned.m16n8k8.row.col.f32.tf32.tf32.f32 "
        "{%0,%1,%2,%3}, {%4,%5,%6,%7}, {%8,%9}, {%0,%1,%2,%3};"
        : "+f"(c[0]), "+f"(c[1]), "+f"(c[2]), "+f"(c[3])
        : "r"(a[0]), "r"(a[1]), "r"(a[2]), "r"(a[3]),
          "r"(b[0]), "r"(b[1]));
}

// ===========================================================================
// Elementwise tf32 rounding: out[i] = rna_tf32(in[i])  (n % 4 == 0)
// ===========================================================================
__global__ void round_kernel(const float* __restrict__ in,
                             float* __restrict__ out, int n)
{
    int i = (blockIdx.x * blockDim.x + threadIdx.x) * 4;
    if (i < n) {
        float4 f = *(const float4*)(in + i);
        f.x = rnd_tf32(f.x); f.y = rnd_tf32(f.y);
        f.z = rnd_tf32(f.z); f.w = rnd_tf32(f.w);
        *(float4*)(out + i) = f;
    }
}

// ===========================================================================
// Weight transpose + tf32 rounding: out[C,R] = rna_tf32(in[R,C]^T)
// ===========================================================================
__global__ void transpose_kernel(const float* __restrict__ in,
                                 float* __restrict__ out, int R, int C)
{
    __shared__ float t[32][33];
    int bx = blockIdx.x * 32, by = blockIdx.y * 32;
    #pragma unroll
    for (int i = 0; i < 32; i += 8)
        t[threadIdx.y + i][threadIdx.x] =
            in[(size_t)(by + threadIdx.y + i) * C + bx + threadIdx.x];
    __syncthreads();
    #pragma unroll
    for (int i = 0; i < 32; i += 8)
        out[(size_t)(bx + threadIdx.y + i) * R + by + threadIdx.x] =
            rnd_tf32(t[threadIdx.x][threadIdx.y + i]);
}

// ===========================================================================
// tf32 mma.sync GEMM with bias: out[M,N] = A[M,K] @ Bt[N,K]^T + bias[N]
// A and Bt MUST be pre-rounded to tf32 bit patterns (raw-bit fragments).
// RND: round output to tf32 (for tensors consumed by later mma stages).
// 2 CTAs/SM (reg-capped to 128) for cross-CTA pipeline-bubble overlap.
// ===========================================================================
#define KCH 32
#define PAD 36
#define OPER_W (128*PAD)
#define SMEM_GEMM (4*OPER_W*4)

template<bool RND>
__global__ void __launch_bounds__(256, 2) gemm_mma(const float* __restrict__ A,
                                                   const float* __restrict__ Bt,
                                                   const float* __restrict__ bias,
                                                   float* __restrict__ out,
                                                   int M, int N, int K)
{
    extern __shared__ float sm[];
    float* As = sm;
    float* Bs = sm + 2*OPER_W;
    const uint32_t As_u = smem_u32(As);
    const uint32_t Bs_u = smem_u32(Bs);

    const int tid  = threadIdx.x;
    const int wid  = tid >> 5;
    const int lane = tid & 31;
    const int wm   = (wid & 3) * 32;
    const int wn   = (wid >> 2) * 64;
    const int grp  = lane >> 2;
    const int qd   = lane & 3;

    const int bm = blockIdx.y * 128;
    const int bn = blockIdx.x * 128;
    const float* Ag = A  + (size_t)bm * K;
    const float* Bg = Bt + (size_t)bn * K;

    float acc[2][8][4];
    #pragma unroll
    for (int t = 0; t < 2; t++)
        #pragma unroll
        for (int n = 0; n < 8; n++)
            #pragma unroll
            for (int i = 0; i < 4; i++) acc[t][n][i] = 0.f;

    const int NC = K / KCH;

    auto load_stage = [&](int kc, int s) {
        const int koff = kc * KCH;
        const uint32_t sa = As_u + (uint32_t)s * OPER_W * 4;
        const uint32_t sb = Bs_u + (uint32_t)s * OPER_W * 4;
        #pragma unroll
        for (int i = 0; i < 4; i++) {
            int idx = tid + i * 256;
            int r = idx >> 3, g = idx & 7;
            uint32_t so = (uint32_t)(r * PAD + g * 4) * 4;
            cp_async16(sa + so, Ag + (size_t)r * K + koff + g * 4);
            cp_async16(sb + so, Bg + (size_t)r * K + koff + g * 4);
        }
    };

    load_stage(0, 0);
    cp_commit();

    for (int kc = 0; kc < NC; kc++) {
        if (kc + 1 < NC) load_stage(kc + 1, (kc + 1) & 1);
        cp_commit();
        cp_wait<1>();
        __syncthreads();

        const float* as = As + (kc & 1) * OPER_W;
        const float* bs = Bs + (kc & 1) * OPER_W;

        #pragma unroll
        for (int k8 = 0; k8 < 4; k8++) {
            const int kk = k8 * 8;
            uint32_t af[2][4], bf[8][2];
            #pragma unroll
            for (int t = 0; t < 2; t++) {
                const float* ap = as + (wm + t*16 + grp) * PAD + kk;
                af[t][0] = __float_as_uint(ap[qd]);
                af[t][1] = __float_as_uint(ap[8*PAD + qd]);
                af[t][2] = __float_as_uint(ap[qd + 4]);
                af[t][3] = __float_as_uint(ap[8*PAD + qd + 4]);
            }
            #pragma unroll
            for (int n = 0; n < 8; n++) {
                const float* bp = bs + (wn + n*8 + grp) * PAD + kk;
                bf[n][0] = __float_as_uint(bp[qd]);
                bf[n][1] = __float_as_uint(bp[qd + 4]);
            }
            #pragma unroll
            for (int t = 0; t < 2; t++)
                #pragma unroll
                for (int n = 0; n < 8; n++)
                    mma_tf32(acc[t][n], af[t], bf[n]);
        }
        __syncthreads();
    }

    #pragma unroll
    for (int t = 0; t < 2; t++) {
        const int r0 = bm + wm + t*16 + grp;
        #pragma unroll
        for (int n = 0; n < 8; n++) {
            const int col = bn + wn + n*8 + 2*qd;
            const float b0 = bias[col], b1 = bias[col + 1];
            float v00 = acc[t][n][0] + b0, v01 = acc[t][n][1] + b1;
            float v10 = acc[t][n][2] + b0, v11 = acc[t][n][3] + b1;
            if (RND) {
                v00 = rnd_tf32(v00); v01 = rnd_tf32(v01);
                v10 = rnd_tf32(v10); v11 = rnd_tf32(v11);
            }
            *(float2*)(out + (size_t)r0 * N + col)       = make_float2(v00, v01);
            *(float2*)(out + (size_t)(r0 + 8) * N + col) = make_float2(v10, v11);
        }
    }
}

// ===========================================================================
// Tensor-core causal flash attention (tf32 mma.sync).
// qkv is pre-rounded to tf32 bit patterns -> K/V/Q fragments are raw bits
// (no cvt in the inner loop). Output written tf32-rounded for the proj GEMM.
// grid = (T/128, H, B), block = 256 (8 warps), 2 CTAs/SM.
// ===========================================================================
#define KS_PAD 68
#define VS_PAD 72
#define KS_W (64*KS_PAD)
#define VS_W (64*VS_PAD)
#define SMEM_ATTN ((2*KS_W + 2*VS_W)*4)

__global__ void __launch_bounds__(256, 2) attn_mma(const float* __restrict__ qkv,
                                                   float* __restrict__ ao)
{
    extern __shared__ float sm[];
    float* ks = sm;                    // [2][64][68]
    float* vs = sm + 2*KS_W;           // [2][64][72]
    const uint32_t ks_u = smem_u32(ks);
    const uint32_t vs_u = smem_u32(vs);

    const int qt = (int)gridDim.x - 1 - (int)blockIdx.x;  // heavy CTAs first
    const int h  = blockIdx.y;
    const int b  = blockIdx.z;
    const int tid  = threadIdx.x;
    const int wid  = tid >> 5;
    const int lane = tid & 31;
    const int grp  = lane >> 2;
    const int qd   = lane & 3;

    const int Q0   = qt * 128;
    const int rmin = Q0 + wid * 16;
    const int rmax = rmin + 15;
    const int row0 = rmin + grp;
    const int row1 = row0 + 8;

    // ---- Q A-fragments: pre-rounded data; *0.125 (2^-3) is exact on tf32 ----
    const float scale = 0.125f;
    uint32_t aQ[8][4];
    {
        const float* q0p = qkv + (size_t)(b*TT + row0)*3*CC + h*DD;
        const float* q1p = qkv + (size_t)(b*TT + row1)*3*CC + h*DD;
        #pragma unroll
        for (int k8 = 0; k8 < 8; k8++) {
            aQ[k8][0] = __float_as_uint(q0p[8*k8 + qd]     * scale);
            aQ[k8][1] = __float_as_uint(q1p[8*k8 + qd]     * scale);
            aQ[k8][2] = __float_as_uint(q0p[8*k8 + qd + 4] * scale);
            aQ[k8][3] = __float_as_uint(q1p[8*k8 + qd + 4] * scale);
        }
    }

    float o[8][4];
    #pragma unroll
    for (int n = 0; n < 8; n++)
        #pragma unroll
        for (int i = 0; i < 4; i++) o[n][i] = 0.f;
    float m0 = -1e30f, m1 = -1e30f, l0 = 0.f, l1 = 0.f;

    const int KT = 2*qt + 2;

    auto load_kv = [&](int kt, int s) {
        const float* kg = qkv + (size_t)(b*TT + kt*64)*3*CC + CC + h*DD;
        const float* vg = kg + CC;
        const uint32_t kb = ks_u + (uint32_t)s * KS_W * 4;
        const uint32_t vb = vs_u + (uint32_t)s * VS_W * 4;
        #pragma unroll
        for (int i = 0; i < 4; i++) {
            int idx = tid + i*256;
            int r = idx >> 4, c4 = idx & 15;
            cp_async16(kb + (uint32_t)(r*KS_PAD + c4*4)*4,
                       kg + (size_t)r*3*CC + c4*4);
            cp_async16(vb + (uint32_t)(r*VS_PAD + c4*4)*4,
                       vg + (size_t)r*3*CC + c4*4);
        }
    };

    load_kv(0, 0); cp_commit();
    load_kv(1, 1); cp_commit();

    for (int kt = 0; kt < KT; kt++) {
        if (kt + 1 < KT) cp_wait<1>(); else cp_wait<0>();
        __syncthreads();

        const float* kss = ks + (kt & 1) * KS_W;
        const float* vss = vs + (kt & 1) * VS_W;
        const int kb = kt * 64;

        if (kb <= rmax) {                       // warp-uniform visibility
            // ---- S = Q @ K^T (raw-bit B fragments) ----
            float s[8][4];
            #pragma unroll
            for (int n = 0; n < 8; n++)
                #pragma unroll
                for (int i = 0; i < 4; i++) s[n][i] = 0.f;

            #pragma unroll
            for (int k8 = 0; k8 < 8; k8++) {
                #pragma unroll
                for (int n8 = 0; n8 < 8; n8++) {
                    const float* kp = kss + (8*n8 + grp)*KS_PAD + 8*k8;
                    uint32_t bk[2];
                    bk[0] = __float_as_uint(kp[qd]);
                    bk[1] = __float_as_uint(kp[qd + 4]);
                    mma_tf32(s[n8], aQ[k8], bk);
                }
            }

            // ---- causal mask (only on partial tiles) ----
            if (kb + 63 > rmin) {
                #pragma unroll
                for (int n8 = 0; n8 < 8; n8++) {
                    const int c0 = kb + 8*n8 + 2*qd;
                    if (c0     > row0) s[n8][0] = -1e30f;
                    if (c0 + 1 > row0) s[n8][1] = -1e30f;
                    if (c0     > row1) s[n8][2] = -1e30f;
                    if (c0 + 1 > row1) s[n8][3] = -1e30f;
                }
            }

            // ---- online softmax on fragments ----
            float mx0 = -1e30f, mx1 = -1e30f;
            #pragma unroll
            for (int n8 = 0; n8 < 8; n8++) {
                mx0 = fmaxf(mx0, fmaxf(s[n8][0], s[n8][1]));
                mx1 = fmaxf(mx1, fmaxf(s[n8][2], s[n8][3]));
            }
            mx0 = fmaxf(mx0, __shfl_xor_sync(0xffffffffu, mx0, 1));
            mx0 = fmaxf(mx0, __shfl_xor_sync(0xffffffffu, mx0, 2));
            mx1 = fmaxf(mx1, __shfl_xor_sync(0xffffffffu, mx1, 1));
            mx1 = fmaxf(mx1, __shfl_xor_sync(0xffffffffu, mx1, 2));

            const float mn0 = fmaxf(m0, mx0);
            const float mn1 = fmaxf(m1, mx1);
            const float al0 = __expf(m0 - mn0);
            const float al1 = __expf(m1 - mn1);
            m0 = mn0; m1 = mn1;
            l0 *= al0; l1 *= al1;
            #pragma unroll
            for (int n8 = 0; n8 < 8; n8++) {
                o[n8][0] *= al0; o[n8][1] *= al0;
                o[n8][2] *= al1; o[n8][3] *= al1;
            }
            #pragma unroll
            for (int n8 = 0; n8 < 8; n8++) {
                s[n8][0] = __expf(s[n8][0] - m0);
                s[n8][1] = __expf(s[n8][1] - m0);
                s[n8][2] = __expf(s[n8][2] - m1);
                s[n8][3] = __expf(s[n8][3] - m1);
                l0 += s[n8][0] + s[n8][1];
                l1 += s[n8][2] + s[n8][3];
            }

            // ---- O += P @ V  (P: C-layout -> A-layout via quad shuffles) ----
            const int srcA = (lane & ~3) | (qd >> 1);
            const int srcB = srcA + 2;
            const bool odd = (qd & 1);
            #pragma unroll
            for (int j = 0; j < 8; j++) {
                const float t00 = __shfl_sync(0xffffffffu, s[j][0], srcA);
                const float t01 = __shfl_sync(0xffffffffu, s[j][1], srcA);
                const float t10 = __shfl_sync(0xffffffffu, s[j][0], srcB);
                const float t11 = __shfl_sync(0xffffffffu, s[j][1], srcB);
                const float t20 = __shfl_sync(0xffffffffu, s[j][2], srcA);
                const float t21 = __shfl_sync(0xffffffffu, s[j][3], srcA);
                const float t30 = __shfl_sync(0xffffffffu, s[j][2], srcB);
                const float t31 = __shfl_sync(0xffffffffu, s[j][3], srcB);
                uint32_t ap[4];
                ap[0] = f2tf32(odd ? t01 : t00);
                ap[1] = f2tf32(odd ? t21 : t20);
                ap[2] = f2tf32(odd ? t11 : t10);
                ap[3] = f2tf32(odd ? t31 : t30);

                const float* vrow0 = vss + (8*j + qd) * VS_PAD;
                const float* vrow1 = vss + (8*j + qd + 4) * VS_PAD;
                #pragma unroll
                for (int n8 = 0; n8 < 8; n8++) {
                    uint32_t bv[2];
                    bv[0] = __float_as_uint(vrow0[8*n8 + grp]);
                    bv[1] = __float_as_uint(vrow1[8*n8 + grp]);
                    mma_tf32(o[n8], ap, bv);
                }
            }
        }

        __syncthreads();
        if (kt + 2 < KT) { load_kv(kt + 2, kt & 1); cp_commit(); }
    }

    // ---- finalize: row sums, normalize, write (tf32-rounded for proj) ----
    l0 += __shfl_xor_sync(0xffffffffu, l0, 1);
    l0 += __shfl_xor_sync(0xffffffffu, l0, 2);
    l1 += __shfl_xor_sync(0xffffffffu, l1, 1);
    l1 += __shfl_xor_sync(0xffffffffu, l1, 2);
    const float inv0 = 1.f / l0;
    const float inv1 = 1.f / l1;

    float* o0 = ao + (size_t)(b*TT + row0)*CC + h*DD;
    float* o1 = ao + (size_t)(b*TT + row1)*CC + h*DD;
    #pragma unroll
    for (int n8 = 0; n8 < 8; n8++) {
        const int col = 8*n8 + 2*qd;
        *(float2*)(o0 + col) = make_float2(rnd_tf32(o[n8][0]*inv0),
                                           rnd_tf32(o[n8][1]*inv0));
        *(float2*)(o1 + col) = make_float2(rnd_tf32(o[n8][2]*inv1),
                                           rnd_tf32(o[n8][3]*inv1));
    }
}

// ===========================================================================
extern "C" void kernel_launch(void* const* d_in, const int* in_sizes, int n_in,
                              void* d_out, int out_size)
{
    const float* x     = (const float*)d_in[0];
    const float* Wqkv  = (const float*)d_in[1];
    const float* bqkv  = (const float*)d_in[2];
    const float* Wproj = (const float*)d_in[3];
    const float* bproj = (const float*)d_in[4];
    float* out = (float*)d_out;

    float *qkv = nullptr, *ao = nullptr, *wt = nullptr, *wt2 = nullptr, *xr = nullptr;
    cudaGetSymbolAddress((void**)&qkv, g_qkv);
    cudaGetSymbolAddress((void**)&ao,  g_ao);
    cudaGetSymbolAddress((void**)&wt,  g_wt);
    cudaGetSymbolAddress((void**)&wt2, g_wt2);
    cudaGetSymbolAddress((void**)&xr,  g_xr);

    static bool attr_set = false;
    if (!attr_set) {
        cudaFuncSetAttribute(gemm_mma<true>,
                             cudaFuncAttributeMaxDynamicSharedMemorySize, SMEM_GEMM);
        cudaFuncSetAttribute(gemm_mma<false>,
                             cudaFuncAttributeMaxDynamicSharedMemorySize, SMEM_GEMM);
        cudaFuncSetAttribute(attn_mma,
                             cudaFuncAttributeMaxDynamicSharedMemorySize, SMEM_ATTN);
        attr_set = true;
    }

    // Pre-round x; transpose+round weights
    round_kernel<<<(MM*CC/4 + 255)/256, 256>>>(x, xr, MM*CC);
    transpose_kernel<<<dim3(3*CC/32, CC/32), dim3(32, 8)>>>(Wqkv, wt, CC, 3*CC);
    transpose_kernel<<<dim3(CC/32,  CC/32), dim3(32, 8)>>>(Wproj, wt2, CC, CC);

    // 1) QKV projection (output rounded to tf32 for attention)
    gemm_mma<true><<<dim3(3*CC/128, MM/128), 256, SMEM_GEMM>>>(xr, wt, bqkv, qkv,
                                                               MM, 3*CC, CC);
    // 2) Causal attention (tensor-core flash attention, raw-bit fragments)
    attn_mma<<<dim3(TT/128, HH, BB), 256, SMEM_ATTN>>>(qkv, ao);

    // 3) Output projection (final output stays fp32)
    gemm_mma<false><<<dim3(CC/128, MM/128), 256, SMEM_GEMM>>>(ao, wt2, bproj, out,
                                                              MM, CC, CC);
}

// round 13
// speedup vs baseline: 5.1319x; 1.0810x over previous
#include <cuda_runtime.h>
#include <math.h>
#include <cstdint>

#define BB 2
#define TT 2048
#define CC 1024
#define HH 16
#define DD 64
#define MM (BB*TT)   // 4096 rows

// Scratch (allocation-free: __device__ globals)
__device__ float g_qkv[(size_t)BB*TT*3*CC];  // [B,T,3C]  (tf32-rounded)
__device__ float g_ao [(size_t)BB*TT*CC];    // [B,T,C]   (tf32-rounded)
__device__ float g_wt [(size_t)3*CC*CC];     // W_qkv^T   (tf32-rounded)
__device__ float g_wt2[(size_t)CC*CC];       // W_proj^T  (tf32-rounded)
__device__ float g_xr [(size_t)MM*CC];       // x         (tf32-rounded)

// ===========================================================================
// helpers (sm_80-era only: cp.async + mma.sync + ldmatrix; nothing 'a'-gated)
// ===========================================================================
__device__ __forceinline__ uint32_t smem_u32(const void* p) {
    uint32_t a;
    asm("{ .reg .u64 t; cvta.to.shared.u64 t, %1; cvt.u32.u64 %0, t; }"
        : "=r"(a) : "l"(p));
    return a;
}
__device__ __forceinline__ void cp_async16(uint32_t dst, const void* src) {
    asm volatile("cp.async.cg.shared.global [%0], [%1], 16;\n"
                 :: "r"(dst), "l"(src));
}
__device__ __forceinline__ void cp_commit() {
    asm volatile("cp.async.commit_group;\n" ::: "memory");
}
template<int N> __device__ __forceinline__ void cp_wait() {
    asm volatile("cp.async.wait_group %0;\n" :: "n"(N) : "memory");
}
__device__ __forceinline__ uint32_t f2tf32(float f) {
    uint32_t r;
    asm("cvt.rna.tf32.f32 %0, %1;" : "=r"(r) : "f"(f));
    return r;
}
__device__ __forceinline__ float rnd_tf32(float f) {
    return __uint_as_float(f2tf32(f));
}
__device__ __forceinline__ void mma_tf32(float c[4],
                                         const uint32_t a[4],
                                         const uint32_t b0,
                                         const uint32_t b1) {
    asm volatile(
        "mma.sync.aligned.m16n8k8.row.col.f32.tf32.tf32.f32 "
        "{%0,%1,%2,%3}, {%4,%5,%6,%7}, {%8,%9}, {%0,%1,%2,%3};"
        : "+f"(c[0]), "+f"(c[1]), "+f"(c[2]), "+f"(c[3])
        : "r"(a[0]), "r"(a[1]), "r"(a[2]), "r"(a[3]),
          "r"(b0), "r"(b1));
}
// 4x (8 rows x 16B) matrix load: one tf32 A-frag (16x8) or two B-frags (16x8)
__device__ __forceinline__ void ldsm_x4(uint32_t r[4], uint32_t addr) {
    asm volatile("ldmatrix.sync.aligned.m8n8.x4.shared.b16 {%0,%1,%2,%3}, [%4];"
        : "=r"(r[0]), "=r"(r[1]), "=r"(r[2]), "=r"(r[3]) : "r"(addr));
}

// ===========================================================================
// Elementwise tf32 rounding: out[i] = rna_tf32(in[i])  (n % 4 == 0)
// ===========================================================================
__global__ void round_kernel(const float* __restrict__ in,
                             float* __restrict__ out, int n)
{
    int i = (blockIdx.x * blockDim.x + threadIdx.x) * 4;
    if (i < n) {
        float4 f = *(const float4*)(in + i);
        f.x = rnd_tf32(f.x); f.y = rnd_tf32(f.y);
        f.z = rnd_tf32(f.z); f.w = rnd_tf32(f.w);
        *(float4*)(out + i) = f;
    }
}

// ===========================================================================
// Weight transpose + tf32 rounding: out[C,R] = rna_tf32(in[R,C]^T)
// ===========================================================================
__global__ void transpose_kernel(const float* __restrict__ in,
                                 float* __restrict__ out, int R, int C)
{
    __shared__ float t[32][33];
    int bx = blockIdx.x * 32, by = blockIdx.y * 32;
    #pragma unroll
    for (int i = 0; i < 32; i += 8)
        t[threadIdx.y + i][threadIdx.x] =
            in[(size_t)(by + threadIdx.y + i) * C + bx + threadIdx.x];
    __syncthreads();
    #pragma unroll
    for (int i = 0; i < 32; i += 8)
        out[(size_t)(bx + threadIdx.y + i) * R + by + threadIdx.x] =
            rnd_tf32(t[threadIdx.x][threadIdx.y + i]);
}

// ===========================================================================
// tf32 mma.sync GEMM with bias: out[M,N] = A[M,K] @ Bt[N,K]^T + bias[N]
// Operands pre-rounded tf32. ldmatrix fragment loads. 3-stage cp.async
// pipeline, ONE __syncthreads per K-chunk. 2 CTAs/SM.
// ===========================================================================
#define KCH 32
#define PAD 36
#define OPER_W (128*PAD)                  // floats per operand per stage
#define SMEM_GEMM (6*OPER_W*4)            // 3 stages * 2 operands

template<bool RND>
__global__ void __launch_bounds__(256, 2) gemm_mma(const float* __restrict__ A,
                                                   const float* __restrict__ Bt,
                                                   const float* __restrict__ bias,
                                                   float* __restrict__ out,
                                                   int M, int N, int K)
{
    extern __shared__ float sm[];
    const uint32_t As_u = smem_u32(sm);
    const uint32_t Bs_u = As_u + 3*OPER_W*4;

    const int tid  = threadIdx.x;
    const int wid  = tid >> 5;
    const int lane = tid & 31;
    const int wm   = (wid & 3) * 32;
    const int wn   = (wid >> 2) * 64;
    const int grp  = lane >> 2;
    const int qd   = lane & 3;

    const int bm = blockIdx.y * 128;
    const int bn = blockIdx.x * 128;
    const float* Ag = A  + (size_t)bm * K;
    const float* Bg = Bt + (size_t)bn * K;

    // ldmatrix per-lane offsets (floats, within a stage)
    const uint32_t aoff0 = (uint32_t)((wm + (lane & 15)) * PAD + ((lane >> 4) << 2));
    const uint32_t aoff1 = aoff0 + 16 * PAD;
    const uint32_t boffb = (uint32_t)((wn + ((lane >> 4) << 3) + (lane & 7)) * PAD
                                      + (((lane >> 3) & 1) << 2));

    float acc[2][8][4];
    #pragma unroll
    for (int t = 0; t < 2; t++)
        #pragma unroll
        for (int n = 0; n < 8; n++)
            #pragma unroll
            for (int i = 0; i < 4; i++) acc[t][n][i] = 0.f;

    const int NC = K / KCH;

    auto load_stage = [&](int kc, int s) {
        const int koff = kc * KCH;
        const uint32_t sa = As_u + (uint32_t)s * OPER_W * 4;
        const uint32_t sb = Bs_u + (uint32_t)s * OPER_W * 4;
        #pragma unroll
        for (int i = 0; i < 4; i++) {
            int idx = tid + i * 256;
            int r = idx >> 3, g = idx & 7;
            uint32_t so = (uint32_t)(r * PAD + g * 4) * 4;
            cp_async16(sa + so, Ag + (size_t)r * K + koff + g * 4);
            cp_async16(sb + so, Bg + (size_t)r * K + koff + g * 4);
        }
    };

    load_stage(0, 0); cp_commit();
    load_stage(1, 1); cp_commit();
    cp_wait<1>();
    __syncthreads();           // stage 0 ready

    for (int kc = 0; kc < NC; kc++) {
        if (kc + 2 < NC) load_stage(kc + 2, (kc + 2) % 3);
        cp_commit();

        const int slot = kc % 3;
        const uint32_t as_b = As_u + (uint32_t)slot * OPER_W * 4;
        const uint32_t bs_b = Bs_u + (uint32_t)slot * OPER_W * 4;

        #pragma unroll
        for (int k8 = 0; k8 < 4; k8++) {
            const uint32_t kk = k8 * 8;
            uint32_t af[2][4];
            ldsm_x4(af[0], as_b + (aoff0 + kk) * 4);
            ldsm_x4(af[1], as_b + (aoff1 + kk) * 4);
            #pragma unroll
            for (int n8 = 0; n8 < 8; n8 += 2) {
                uint32_t bf[4];
                ldsm_x4(bf, bs_b + (boffb + (uint32_t)(n8 * 8 * PAD) + kk) * 4);
                mma_tf32(acc[0][n8],     af[0], bf[0], bf[1]);
                mma_tf32(acc[1][n8],     af[1], bf[0], bf[1]);
                mma_tf32(acc[0][n8 + 1], af[0], bf[2], bf[3]);
                mma_tf32(acc[1][n8 + 1], af[1], bf[2], bf[3]);
            }
        }

        cp_wait<1>();          // stage kc+1 ready; stage kc+2 may be in flight
        __syncthreads();       // also frees slot (kc)%3 for the kc+3 load
    }

    #pragma unroll
    for (int t = 0; t < 2; t++) {
        const int r0 = bm + wm + t*16 + grp;
        #pragma unroll
        for (int n = 0; n < 8; n++) {
            const int col = bn + wn + n*8 + 2*qd;
            const float b0 = bias[col], b1 = bias[col + 1];
            float v00 = acc[t][n][0] + b0, v01 = acc[t][n][1] + b1;
            float v10 = acc[t][n][2] + b0, v11 = acc[t][n][3] + b1;
            if (RND) {
                v00 = rnd_tf32(v00); v01 = rnd_tf32(v01);
                v10 = rnd_tf32(v10); v11 = rnd_tf32(v11);
            }
            *(float2*)(out + (size_t)r0 * N + col)       = make_float2(v00, v01);
            *(float2*)(out + (size_t)(r0 + 8) * N + col) = make_float2(v10, v11);
        }
    }
}

// ===========================================================================
// Tensor-core causal flash attention (tf32 mma.sync).
// qkv pre-rounded tf32. K fragments via ldmatrix. 3-stage K/V pipeline,
// ONE __syncthreads per key tile. 2 CTAs/SM.
// ===========================================================================
#define KS_PAD 68
#define VS_PAD 72
#define KS_W (64*KS_PAD)
#define VS_W (64*VS_PAD)
#define SMEM_ATTN (3*(KS_W + VS_W)*4)

__global__ void __launch_bounds__(256, 2) attn_mma(const float* __restrict__ qkv,
                                                   float* __restrict__ ao)
{
    extern __shared__ float sm[];
    float* ks = sm;                    // [3][64][68]
    float* vs = sm + 3*KS_W;           // [3][64][72]
    const uint32_t ks_u = smem_u32(ks);
    const uint32_t vs_u = smem_u32(vs);

    const int qt = (int)gridDim.x - 1 - (int)blockIdx.x;  // heavy CTAs first
    const int h  = blockIdx.y;
    const int b  = blockIdx.z;
    const int tid  = threadIdx.x;
    const int wid  = tid >> 5;
    const int lane = tid & 31;
    const int grp  = lane >> 2;
    const int qd   = lane & 3;

    const int Q0   = qt * 128;
    const int rmin = Q0 + wid * 16;
    const int rmax = rmin + 15;
    const int row0 = rmin + grp;
    const int row1 = row0 + 8;

    // K-fragment ldmatrix per-lane offset (floats, within a stage)
    const uint32_t koffb = (uint32_t)((((lane >> 4) << 3) + (lane & 7)) * KS_PAD
                                      + (((lane >> 3) & 1) << 2));

    // ---- Q A-fragments: pre-rounded data; *0.125 (2^-3) exact on tf32 ----
    const float scale = 0.125f;
    uint32_t aQ[8][4];
    {
        const float* q0p = qkv + (size_t)(b*TT + row0)*3*CC + h*DD;
        const float* q1p = qkv + (size_t)(b*TT + row1)*3*CC + h*DD;
        #pragma unroll
        for (int k8 = 0; k8 < 8; k8++) {
            aQ[k8][0] = __float_as_uint(q0p[8*k8 + qd]     * scale);
            aQ[k8][1] = __float_as_uint(q1p[8*k8 + qd]     * scale);
            aQ[k8][2] = __float_as_uint(q0p[8*k8 + qd + 4] * scale);
            aQ[k8][3] = __float_as_uint(q1p[8*k8 + qd + 4] * scale);
        }
    }

    float o[8][4];
    #pragma unroll
    for (int n = 0; n < 8; n++)
        #pragma unroll
        for (int i = 0; i < 4; i++) o[n][i] = 0.f;
    float m0 = -1e30f, m1 = -1e30f, l0 = 0.f, l1 = 0.f;

    const int KT = 2*qt + 2;

    auto load_kv = [&](int kt, int s) {
        const float* kg = qkv + (size_t)(b*TT + kt*64)*3*CC + CC + h*DD;
        const float* vg = kg + CC;
        const uint32_t kb = ks_u + (uint32_t)s * KS_W * 4;
        const uint32_t vb = vs_u + (uint32_t)s * VS_W * 4;
        #pragma unroll
        for (int i = 0; i < 4; i++) {
            int idx = tid + i*256;
            int r = idx >> 4, c4 = idx & 15;
            cp_async16(kb + (uint32_t)(r*KS_PAD + c4*4)*4,
                       kg + (size_t)r*3*CC + c4*4);
            cp_async16(vb + (uint32_t)(r*VS_PAD + c4*4)*4,
                       vg + (size_t)r*3*CC + c4*4);
        }
    };

    load_kv(0, 0); cp_commit();
    load_kv(1, 1); cp_commit();
    cp_wait<1>();
    __syncthreads();           // tile 0 ready

    for (int kt = 0; kt < KT; kt++) {
        if (kt + 2 < KT) load_kv(kt + 2, (kt + 2) % 3);
        cp_commit();

        const int slot = kt % 3;
        const uint32_t ksb = ks_u + (uint32_t)slot * KS_W * 4;
        const float* vss = vs + slot * VS_W;
        const int kb = kt * 64;

        if (kb <= rmax) {                       // warp-uniform visibility
            // ---- S = Q @ K^T (K frags via ldmatrix) ----
            float s[8][4];
            #pragma unroll
            for (int n = 0; n < 8; n++)
                #pragma unroll
                for (int i = 0; i < 4; i++) s[n][i] = 0.f;

            #pragma unroll
            for (int k8 = 0; k8 < 8; k8++) {
                const uint32_t kk = k8 * 8;
                #pragma unroll
                for (int n8 = 0; n8 < 8; n8 += 2) {
                    uint32_t bk[4];
                    ldsm_x4(bk, ksb + (koffb + (uint32_t)(n8 * 8 * KS_PAD) + kk) * 4);
                    mma_tf32(s[n8],     aQ[k8], bk[0], bk[1]);
                    mma_tf32(s[n8 + 1], aQ[k8], bk[2], bk[3]);
                }
            }

            // ---- causal mask (only on partial tiles) ----
            if (kb + 63 > rmin) {
                #pragma unroll
                for (int n8 = 0; n8 < 8; n8++) {
                    const int c0 = kb + 8*n8 + 2*qd;
                    if (c0     > row0) s[n8][0] = -1e30f;
                    if (c0 + 1 > row0) s[n8][1] = -1e30f;
                    if (c0     > row1) s[n8][2] = -1e30f;
                    if (c0 + 1 > row1) s[n8][3] = -1e30f;
                }
            }

            // ---- online softmax on fragments ----
            float mx0 = -1e30f, mx1 = -1e30f;
            #pragma unroll
            for (int n8 = 0; n8 < 8; n8++) {
                mx0 = fmaxf(mx0, fmaxf(s[n8][0], s[n8][1]));
                mx1 = fmaxf(mx1, fmaxf(s[n8][2], s[n8][3]));
            }
            mx0 = fmaxf(mx0, __shfl_xor_sync(0xffffffffu, mx0, 1));
            mx0 = fmaxf(mx0, __shfl_xor_sync(0xffffffffu, mx0, 2));
            mx1 = fmaxf(mx1, __shfl_xor_sync(0xffffffffu, mx1, 1));
            mx1 = fmaxf(mx1, __shfl_xor_sync(0xffffffffu, mx1, 2));

            const float mn0 = fmaxf(m0, mx0);
            const float mn1 = fmaxf(m1, mx1);
            const float al0 = __expf(m0 - mn0);
            const float al1 = __expf(m1 - mn1);
            m0 = mn0; m1 = mn1;
            l0 *= al0; l1 *= al1;
            #pragma unroll
            for (int n8 = 0; n8 < 8; n8++) {
                o[n8][0] *= al0; o[n8][1] *= al0;
                o[n8][2] *= al1; o[n8][3] *= al1;
            }
            #pragma unroll
            for (int n8 = 0; n8 < 8; n8++) {
                s[n8][0] = __expf(s[n8][0] - m0);
                s[n8][1] = __expf(s[n8][1] - m0);
                s[n8][2] = __expf(s[n8][2] - m1);
                s[n8][3] = __expf(s[n8][3] - m1);
                l0 += s[n8][0] + s[n8][1];
                l1 += s[n8][2] + s[n8][3];
            }

            // ---- O += P @ V  (P: C-layout -> A-layout via quad shuffles) ----
            const int srcA = (lane & ~3) | (qd >> 1);
            const int srcB = srcA + 2;
            const bool odd = (qd & 1);
            #pragma unroll
            for (int j = 0; j < 8; j++) {
                const float t00 = __shfl_sync(0xffffffffu, s[j][0], srcA);
                const float t01 = __shfl_sync(0xffffffffu, s[j][1], srcA);
                const float t10 = __shfl_sync(0xffffffffu, s[j][0], srcB);
                const float t11 = __shfl_sync(0xffffffffu, s[j][1], srcB);
                const float t20 = __shfl_sync(0xffffffffu, s[j][2], srcA);
                const float t21 = __shfl_sync(0xffffffffu, s[j][3], srcA);
                const float t30 = __shfl_sync(0xffffffffu, s[j][2], srcB);
                const float t31 = __shfl_sync(0xffffffffu, s[j][3], srcB);
                uint32_t ap[4];
                ap[0] = f2tf32(odd ? t01 : t00);
                ap[1] = f2tf32(odd ? t21 : t20);
                ap[2] = f2tf32(odd ? t11 : t10);
                ap[3] = f2tf32(odd ? t31 : t30);

                const float* vrow0 = vss + (8*j + qd) * VS_PAD;
                const float* vrow1 = vss + (8*j + qd + 4) * VS_PAD;
                #pragma unroll
                for (int n8 = 0; n8 < 8; n8++) {
                    mma_tf32(o[n8], ap,
                             __float_as_uint(vrow0[8*n8 + grp]),
                             __float_as_uint(vrow1[8*n8 + grp]));
                }
            }
        }

        cp_wait<1>();
        __syncthreads();
    }

    // ---- finalize: row sums, normalize, write (tf32-rounded for proj) ----
    l0 += __shfl_xor_sync(0xffffffffu, l0, 1);
    l0 += __shfl_xor_sync(0xffffffffu, l0, 2);
    l1 += __shfl_xor_sync(0xffffffffu, l1, 1);
    l1 += __shfl_xor_sync(0xffffffffu, l1, 2);
    const float inv0 = 1.f / l0;
    const float inv1 = 1.f / l1;

    float* o0 = ao + (size_t)(b*TT + row0)*CC + h*DD;
    float* o1 = ao + (size_t)(b*TT + row1)*CC + h*DD;
    #pragma unroll
    for (int n8 = 0; n8 < 8; n8++) {
        const int col = 8*n8 + 2*qd;
        *(float2*)(o0 + col) = make_float2(rnd_tf32(o[n8][0]*inv0),
                                           rnd_tf32(o[n8][1]*inv0));
        *(float2*)(o1 + col) = make_float2(rnd_tf32(o[n8][2]*inv1),
                                           rnd_tf32(o[n8][3]*inv1));
    }
}

// ===========================================================================
extern "C" void kernel_launch(void* const* d_in, const int* in_sizes, int n_in,
                              void* d_out, int out_size)
{
    const float* x     = (const float*)d_in[0];
    const float* Wqkv  = (const float*)d_in[1];
    const float* bqkv  = (const float*)d_in[2];
    const float* Wproj = (const float*)d_in[3];
    const float* bproj = (const float*)d_in[4];
    float* out = (float*)d_out;

    float *qkv = nullptr, *ao = nullptr, *wt = nullptr, *wt2 = nullptr, *xr = nullptr;
    cudaGetSymbolAddress((void**)&qkv, g_qkv);
    cudaGetSymbolAddress((void**)&ao,  g_ao);
    cudaGetSymbolAddress((void**)&wt,  g_wt);
    cudaGetSymbolAddress((void**)&wt2, g_wt2);
    cudaGetSymbolAddress((void**)&xr,  g_xr);

    static bool attr_set = false;
    if (!attr_set) {
        cudaFuncSetAttribute(gemm_mma<true>,
                             cudaFuncAttributeMaxDynamicSharedMemorySize, SMEM_GEMM);
        cudaFuncSetAttribute(gemm_mma<false>,
                             cudaFuncAttributeMaxDynamicSharedMemorySize, SMEM_GEMM);
        cudaFuncSetAttribute(attn_mma,
                             cudaFuncAttributeMaxDynamicSharedMemorySize, SMEM_ATTN);
        attr_set = true;
    }

    // Pre-round x; transpose+round weights
    round_kernel<<<(MM*CC/4 + 255)/256, 256>>>(x, xr, MM*CC);
    transpose_kernel<<<dim3(3*CC/32, CC/32), dim3(32, 8)>>>(Wqkv, wt, CC, 3*CC);
    transpose_kernel<<<dim3(CC/32,  CC/32), dim3(32, 8)>>>(Wproj, wt2, CC, CC);

    // 1) QKV projection (output rounded to tf32 for attention)
    gemm_mma<true><<<dim3(3*CC/128, MM/128), 256, SMEM_GEMM>>>(xr, wt, bqkv, qkv,
                                                               MM, 3*CC, CC);
    // 2) Causal attention (tensor-core flash attention)
    attn_mma<<<dim3(TT/128, HH, BB), 256, SMEM_ATTN>>>(qkv, ao);

    // 3) Output projection (final output stays fp32)
    gemm_mma<false><<<dim3(CC/128, MM/128), 256, SMEM_GEMM>>>(ao, wt2, bproj, out,
                                                              MM, CC, CC);
}